// round 10
// baseline (speedup 1.0000x reference)
#include <cuda_runtime.h>
#include <cuda_bf16.h>
#include <cstdint>
#include <cstddef>

#define NN   20000
#define EE   320000
#define RR   8
#define HH   4
#define HD   256

typedef __nv_bfloat16 bf16;

// ---------------- device scratch ----------------
__device__ float g_xin [(size_t)NN*HD];
__device__ float g_xw  [(size_t)RR*NN*HD];
__device__ float g_s   [(size_t)NN*64];
__device__ float g_wqk [256*64];
__device__ float g_x1  [(size_t)NN*HD];
__device__ float g_skp [(size_t)NN*HD];
__device__ bf16  g_xinh[(size_t)NN*HD];
__device__ bf16  g_xinl[(size_t)NN*HD];
__device__ bf16  g_x1h [(size_t)NN*HD];
__device__ bf16  g_x1l [(size_t)NN*HD];
__device__ bf16  g_hsh [(size_t)NN*HD];
__device__ bf16  g_hsl [(size_t)NN*HD];
__device__ bf16  g_w1h [(size_t)RR*65536];
__device__ bf16  g_w1l [(size_t)RR*65536];
__device__ bf16  g_w2h [(size_t)RR*65536];
__device__ bf16  g_w2l [(size_t)RR*65536];
__device__ bf16  g_sw1h[65536];
__device__ bf16  g_sw1l[65536];
__device__ bf16  g_sw2h[65536];
__device__ bf16  g_sw2l[65536];
__device__ int g_deg[NN], g_rowptr[NN], g_cur[NN], g_eid[EE];

__device__ __forceinline__ float lrelu01(float v){ return v > 0.f ? v : 0.01f*v; }

__device__ __forceinline__ uint32_t smem_u32(const void* p){
    uint32_t a;
    asm("{ .reg .u64 t; cvta.to.shared.u64 t, %1; cvt.u32.u64 %0, t; }" : "=r"(a) : "l"(p));
    return a;
}
__device__ __forceinline__ void ldsm_x4(uint32_t* r, uint32_t addr){
    asm volatile("ldmatrix.sync.aligned.m8n8.x4.shared.b16 {%0,%1,%2,%3}, [%4];"
        : "=r"(r[0]), "=r"(r[1]), "=r"(r[2]), "=r"(r[3]) : "r"(addr));
}
__device__ __forceinline__ void mma16816(float* d, const uint32_t* a, const uint32_t* b){
    asm volatile("mma.sync.aligned.m16n8k16.row.col.f32.bf16.bf16.f32 "
        "{%0,%1,%2,%3}, {%4,%5,%6,%7}, {%8,%9}, {%0,%1,%2,%3};"
        : "+f"(d[0]), "+f"(d[1]), "+f"(d[2]), "+f"(d[3])
        : "r"(a[0]), "r"(a[1]), "r"(a[2]), "r"(a[3]), "r"(b[0]), "r"(b[1]));
}
__device__ __forceinline__ void cp_async16(uint32_t saddr, const void* g, uint32_t srcsz){
    asm volatile("cp.async.cg.shared.global [%0], [%1], 16, %2;"
                 :: "r"(saddr), "l"(g), "r"(srcsz) : "memory");
}
#define CP_COMMIT() asm volatile("cp.async.commit_group;" ::: "memory")
#define CP_WAIT1()  asm volatile("cp.async.wait_group 1;" ::: "memory")
#define CP_WAIT0()  asm volatile("cp.async.wait_group 0;" ::: "memory")

__device__ __forceinline__ void split2(float v, bf16& h, bf16& l){
    h = __float2bfloat16(v);
    l = __float2bfloat16(v - __bfloat162float(h));
}

__device__ __forceinline__ uint32_t swz(int row, uint32_t colB){
    return (uint32_t)(row*64) + (colB ^ (uint32_t)((row & 6) << 3));
}

// ---------------- x_in build + splits ----------------
__global__ void build_xin(const float* __restrict__ kg, const float* __restrict__ ccle,
                          const int* __restrict__ nid,
                          const float* __restrict__ cw1, const float* __restrict__ cb1,
                          const float* __restrict__ cw2, const float* __restrict__ cb2)
{
    int i = blockIdx.x;
    int t = threadIdx.x;               // 128
    int nd = nid[i];
    __shared__ float c4[4];
    __shared__ float hdn[32];
    if (t < 4) c4[t] = ccle[(size_t)nd*4 + t];
    float v0 = kg[(size_t)nd*128 + t];
    g_xin[(size_t)i*HD + t] = v0;
    bf16 h, l; split2(v0, h, l);
    g_xinh[(size_t)i*HD + t] = h; g_xinl[(size_t)i*HD + t] = l;
    __syncthreads();
    if (t < 32){
        float a = cb1[t];
        #pragma unroll
        for (int j = 0; j < 4; j++) a += c4[j]*cw1[j*32 + t];
        hdn[t] = lrelu01(a);
    }
    __syncthreads();
    float o = cb2[t];
    #pragma unroll 8
    for (int j = 0; j < 32; j++) o += hdn[j]*cw2[j*128 + t];
    g_xin[(size_t)i*HD + 128 + t] = o;
    split2(o, h, l);
    g_xinh[(size_t)i*HD + 128 + t] = h; g_xinl[(size_t)i*HD + 128 + t] = l;
}

// ---------------- W split-transpose ----------------
__global__ void splitW(const float* __restrict__ w, bf16* __restrict__ oh, bf16* __restrict__ ol)
{
    __shared__ float tile[32][33];
    int z = blockIdx.z;
    const float* wz = w + (size_t)z*65536;
    int tx = threadIdx.x, ty = threadIdx.y;   // 32x8
    int k0 = blockIdx.x*32, n0 = blockIdx.y*32;
    #pragma unroll
    for (int i = ty; i < 32; i += 8)
        tile[i][tx] = wz[(size_t)(k0+i)*256 + n0 + tx];
    __syncthreads();
    #pragma unroll
    for (int i = ty; i < 32; i += 8){
        float v = tile[tx][i];
        bf16 h, l; split2(v, h, l);
        size_t o = (size_t)z*65536 + (size_t)(n0+i)*256 + k0 + tx;
        oh[o] = h; ol[o] = l;
    }
}

// ---------------- 3-stage cp.async HMMA GEMM (XOR-swizzled smem) ----------------
__device__ __forceinline__ void hm_load(uint32_t sb, int stg, int kc,
    const bf16* __restrict__ Ah, const bf16* __restrict__ Al,
    const bf16* __restrict__ WhB, const bf16* __restrict__ WlB,
    int row0, int M, int t)
{
    const int kofs = kc*32;
    const uint32_t stBase = sb + (uint32_t)stg*32768u;
    #pragma unroll
    for (int j = 0; j < 2; j++){
        int g   = j*256 + t;
        int row = g >> 2;
        uint32_t cb = (uint32_t)((g & 3) * 16);
        uint32_t so = stBase + swz(row, cb);
        uint32_t ok = (row0 + row < M) ? 16u : 0u;
        size_t go = (size_t)(row0 + row)*256 + kofs + (cb >> 1);
        cp_async16(so,          Ah + go, ok);
        cp_async16(so +  8192u, Al + go, ok);
        size_t gw = (size_t)row*256 + kofs + (cb >> 1);
        cp_async16(so + 16384u, WhB + gw, 16u);
        cp_async16(so + 24576u, WlB + gw, 16u);
    }
}

template<int MODE>
__global__ void __launch_bounds__(256, 2)
hmma_gemm(const bf16* __restrict__ Ah, const bf16* __restrict__ Al,
          const bf16* __restrict__ Wh, const bf16* __restrict__ Wl,
          float* __restrict__ Cf, bf16* __restrict__ Ch, bf16* __restrict__ Cl,
          int M, const float* __restrict__ bias,
          size_t wStride, size_t cStride)
{
    extern __shared__ char sm[];
    const uint32_t sb = smem_u32(sm);
    const int t = threadIdx.x, lane = t & 31, wid = t >> 5;
    const int wm = wid & 3, wn = wid >> 2;
    const int row0 = blockIdx.x*128;
    const int col0 = blockIdx.y*128;
    const bf16* WhB = Wh + wStride*blockIdx.z + (size_t)col0*256;
    const bf16* WlB = Wl + wStride*blockIdx.z + (size_t)col0*256;

    float acc[2][8][4];
    #pragma unroll
    for (int i = 0; i < 2; i++)
        #pragma unroll
        for (int j = 0; j < 8; j++)
            #pragma unroll
            for (int q = 0; q < 4; q++) acc[i][j][q] = 0.f;

    const int ar  = lane & 15, ac8 = lane >> 4;
    const int bnl = (lane & 7) + ((lane >> 4) << 3);
    const int bkh = (lane >> 3) & 1;

    hm_load(sb, 0, 0, Ah, Al, WhB, WlB, row0, M, t); CP_COMMIT();
    hm_load(sb, 1, 1, Ah, Al, WhB, WlB, row0, M, t); CP_COMMIT();

    int stg = 0, ldstg = 2;
    for (int kc = 0; kc < 8; kc++){
        if (kc < 7) CP_WAIT1(); else CP_WAIT0();
        __syncthreads();
        if (kc < 6){
            hm_load(sb, ldstg, kc+2, Ah, Al, WhB, WlB, row0, M, t);
            CP_COMMIT();
            if (++ldstg == 3) ldstg = 0;
        }

        const uint32_t stBase = sb + (uint32_t)stg*32768u;
        #pragma unroll
        for (int ks = 0; ks < 2; ks++){
            uint32_t a_h[2][4], a_l[2][4], bw[4][4];
            const uint32_t acol = (uint32_t)(ks*32 + ac8*16);
            #pragma unroll
            for (int i = 0; i < 2; i++){
                int row = wm*32 + i*16 + ar;
                uint32_t addr = stBase + swz(row, acol);
                ldsm_x4(a_h[i], addr);
                ldsm_x4(a_l[i], addr + 8192u);
            }
            const uint32_t bcol = (uint32_t)(ks*32 + bkh*16);
            #pragma unroll
            for (int qd = 0; qd < 4; qd++){
                int row = wn*64 + qd*16 + bnl;
                ldsm_x4(bw[qd], stBase + 16384u + swz(row, bcol));
            }
            #pragma unroll
            for (int i = 0; i < 2; i++)
                #pragma unroll
                for (int j = 0; j < 8; j++)
                    mma16816(acc[i][j], a_h[i], &bw[j>>1][(j&1)*2]);
            #pragma unroll
            for (int i = 0; i < 2; i++)
                #pragma unroll
                for (int j = 0; j < 8; j++)
                    mma16816(acc[i][j], a_l[i], &bw[j>>1][(j&1)*2]);
            #pragma unroll
            for (int qd = 0; qd < 4; qd++){
                int row = wn*64 + qd*16 + bnl;
                ldsm_x4(bw[qd], stBase + 24576u + swz(row, bcol));
            }
            #pragma unroll
            for (int i = 0; i < 2; i++)
                #pragma unroll
                for (int j = 0; j < 8; j++)
                    mma16816(acc[i][j], a_h[i], &bw[j>>1][(j&1)*2]);
        }
        if (++stg == 3) stg = 0;
    }

    const int cr = lane >> 2, cc = (lane & 3)*2;
    #pragma unroll
    for (int i = 0; i < 2; i++){
        #pragma unroll
        for (int rr = 0; rr < 2; rr++){
            int grow = row0 + wm*32 + i*16 + rr*8 + cr;
            if (grow >= M) continue;
            #pragma unroll
            for (int j = 0; j < 8; j++){
                int gcol = col0 + wn*64 + j*8 + cc;
                float v0 = acc[i][j][rr*2+0];
                float v1 = acc[i][j][rr*2+1];
                if (MODE == 0){
                    float2 f; f.x = v0; f.y = v1;
                    *(float2*)(Cf + cStride*blockIdx.z + (size_t)grow*256 + gcol) = f;
                } else if (MODE == 1){
                    v0 = lrelu01(v0 + bias[gcol]);
                    v1 = lrelu01(v1 + bias[gcol+1]);
                    bf16 h0, l0, h1, l1;
                    split2(v0, h0, l0); split2(v1, h1, l1);
                    Ch[(size_t)grow*256 + gcol]   = h0; Ch[(size_t)grow*256 + gcol+1] = h1;
                    Cl[(size_t)grow*256 + gcol]   = l0; Cl[(size_t)grow*256 + gcol+1] = l1;
                } else {
                    float2 f; f.x = v0 + bias[gcol]; f.y = v1 + bias[gcol+1];
                    *(float2*)(Cf + (size_t)grow*256 + gcol) = f;
                }
            }
        }
    }
}

// ---------------- wqk fold + small projection GEMM ----------------
__global__ void make_wqk(const float* __restrict__ w, const float* __restrict__ q,
                         const float* __restrict__ km)
{
    int idx = blockIdx.x*blockDim.x + threadIdx.x;
    int kk  = idx >> 6;
    int j   = idx & 63;
    int isK = (j >= 32);
    int rh  = isK ? j - 32 : j;
    int r   = rh >> 2, h = rh & 3;
    const float* wm = w + ((size_t)r*256 + kk)*256;
    const float* qm = isK ? km : q;
    float a = 0.f;
    #pragma unroll 8
    for (int o = 0; o < 256; o++) a += wm[o]*qm[o*4 + h];
    g_wqk[kk*64 + j] = a;
}

__global__ void gemm_k256_n64(const float* __restrict__ A, const float* __restrict__ W,
                              float* __restrict__ C, int M)
{
    constexpr int BM = 64, BK = 16, BN = 64;
    constexpr int TN = 4, TM = 4;
    __shared__ float As[BK][BM + 4];
    __shared__ float Ws[BK][BN];
    int row0 = blockIdx.x*BM;
    int t  = threadIdx.x;
    int tx = t & 15, ty = t >> 4;
    float acc[TM][TN] = {};
    int aRow = t >> 2;
    int aK4  = (t & 3) * 4;
    for (int k0 = 0; k0 < 256; k0 += BK){
        float4 av = make_float4(0.f,0.f,0.f,0.f);
        int gr = row0 + aRow;
        if (gr < M) av = *(const float4*)(A + (size_t)gr*256 + k0 + aK4);
        As[aK4+0][aRow] = av.x; As[aK4+1][aRow] = av.y;
        As[aK4+2][aRow] = av.z; As[aK4+3][aRow] = av.w;
        {
            int kk = t / 16, j4 = (t % 16) * 4;
            *(float4*)&Ws[kk][j4] = *(const float4*)(W + (size_t)(k0+kk)*64 + j4);
        }
        __syncthreads();
        #pragma unroll
        for (int kk = 0; kk < BK; kk++){
            float a[TM], bb[TN];
            #pragma unroll
            for (int i = 0; i < TM; i++) a[i] = As[kk][ty*TM + i];
            #pragma unroll
            for (int j = 0; j < TN; j++) bb[j] = Ws[kk][tx*TN + j];
            #pragma unroll
            for (int i = 0; i < TM; i++)
                #pragma unroll
                for (int j = 0; j < TN; j++) acc[i][j] += a[i]*bb[j];
        }
        __syncthreads();
    }
    #pragma unroll
    for (int i = 0; i < TM; i++){
        int gr = row0 + ty*TM + i;
        if (gr >= M) continue;
        #pragma unroll
        for (int j = 0; j < TN; j++)
            C[(size_t)gr*64 + tx*TN + j] = acc[i][j];
    }
}

// ---------------- CSR build ----------------
__global__ void zero_deg(){
    int i = blockIdx.x*blockDim.x + threadIdx.x;
    if (i < NN) g_deg[i] = 0;
}
__global__ void hist(const int* __restrict__ dst){
    int e = blockIdx.x*blockDim.x + threadIdx.x;
    if (e < EE) atomicAdd(&g_deg[dst[e]], 1);
}
__global__ void scan_rowptr(){
    __shared__ int wsum[32];
    int t = threadIdx.x, lane = t & 31, wid = t >> 5;
    int beg = t*20, end = beg + 20; if (end > NN) end = NN;
    int s = 0;
    for (int i = beg; i < end; i++) s += g_deg[i];
    int v = s;
    #pragma unroll
    for (int o = 1; o < 32; o <<= 1){
        int u = __shfl_up_sync(0xffffffffu, v, o);
        if (lane >= o) v += u;
    }
    if (lane == 31) wsum[wid] = v;
    __syncthreads();
    if (wid == 0){
        int w = wsum[lane];
        #pragma unroll
        for (int o = 1; o < 32; o <<= 1){
            int u = __shfl_up_sync(0xffffffffu, w, o);
            if (lane >= o) w += u;
        }
        wsum[lane] = w;
    }
    __syncthreads();
    int run = v - s + (wid ? wsum[wid-1] : 0);
    for (int i = beg; i < end; i++){
        g_rowptr[i] = run;
        g_cur[i]    = run;
        run += g_deg[i];
    }
}
__global__ void scatter(const int* __restrict__ dst){
    int e = blockIdx.x*blockDim.x + threadIdx.x;
    if (e >= EE) return;
    int slot = atomicAdd(&g_cur[dst[e]], 1);
    g_eid[slot] = e;
}

// ---------------- warp-per-destination attention + aggregation ----------------
// 256 threads = 8 warps, one dst per warp. No block barriers.
__global__ void edge_fused(const int* __restrict__ src, const int* __restrict__ et,
                           const float* __restrict__ bias,
                           const float* __restrict__ skip,
                           float* __restrict__ out,
                           bf16* __restrict__ oh, bf16* __restrict__ ol)
{
    const int w    = threadIdx.x >> 5;
    const int lane = threadIdx.x & 31;
    const int d    = blockIdx.x*8 + w;
    if (d >= NN) return;
    const int base = g_rowptr[d], deg = g_deg[d];
    const int h0 = lane >> 4;        // head for cols [lane*4, +4)      (0..1)
    const int h1 = 2 + h0;           // head for cols [128+lane*4, +4)  (2..3)

    __shared__ float sl  [8][32][4];
    __shared__ int   ssrc[8][32];
    __shared__ int   srel[8][32];

    float4 acc0a = {0,0,0,0}, acc0b = {0,0,0,0}, acc0c = {0,0,0,0}, acc0d = {0,0,0,0};
    float4 acc1a = {0,0,0,0}, acc1b = {0,0,0,0}, acc1c = {0,0,0,0}, acc1d = {0,0,0,0};
    float m[4], ssum[4];
    #pragma unroll
    for (int h = 0; h < 4; h++){ m[h] = -1e30f; ssum[h] = 0.f; }

    const float* qbase = g_s + (size_t)d*64;

    for (int c0 = 0; c0 < deg; c0 += 32){
        int n = deg - c0; if (n > 32) n = 32;
        float l[4];
        if (lane < n){
            int e = g_eid[base + c0 + lane];
            int s = src[e], r = et[e];
            ssrc[w][lane] = s; srel[w][lane] = r;
            const float* qv = qbase + r*4;
            const float* kv = g_s + (size_t)s*64 + 32 + r*4;
            #pragma unroll
            for (int h = 0; h < 4; h++){
                float v = qv[h] + kv[h];
                l[h] = v > 0.f ? v : 0.2f*v;
            }
        } else {
            #pragma unroll
            for (int h = 0; h < 4; h++) l[h] = -1e30f;
        }
        // warp max per head + online rescale
        float newm[4], scale[4];
        #pragma unroll
        for (int h = 0; h < 4; h++){
            float v = l[h];
            #pragma unroll
            for (int o = 16; o; o >>= 1) v = fmaxf(v, __shfl_xor_sync(0xffffffffu, v, o));
            newm[h]  = fmaxf(m[h], v);
            scale[h] = __expf(m[h] - newm[h]);
            m[h]     = newm[h];
            ssum[h] *= scale[h];
        }
        float s0 = scale[h0], s1 = scale[h1];
        acc0a.x*=s0; acc0a.y*=s0; acc0a.z*=s0; acc0a.w*=s0;
        acc0b.x*=s0; acc0b.y*=s0; acc0b.z*=s0; acc0b.w*=s0;
        acc0c.x*=s0; acc0c.y*=s0; acc0c.z*=s0; acc0c.w*=s0;
        acc0d.x*=s0; acc0d.y*=s0; acc0d.z*=s0; acc0d.w*=s0;
        acc1a.x*=s1; acc1a.y*=s1; acc1a.z*=s1; acc1a.w*=s1;
        acc1b.x*=s1; acc1b.y*=s1; acc1b.z*=s1; acc1b.w*=s1;
        acc1c.x*=s1; acc1c.y*=s1; acc1c.z*=s1; acc1c.w*=s1;
        acc1d.x*=s1; acc1d.y*=s1; acc1d.z*=s1; acc1d.w*=s1;
        // exp + warp sums
        #pragma unroll
        for (int h = 0; h < 4; h++){
            float e = (lane < n) ? __expf(l[h] - m[h]) : 0.f;
            sl[w][lane][h] = e;
            #pragma unroll
            for (int o = 16; o; o >>= 1) e += __shfl_xor_sync(0xffffffffu, e, o);
            ssum[h] += e;
        }
        __syncwarp();

        // weighted message accumulation: 4-deep unroll, 8 independent float4 chains
        const float4* xw4 = (const float4*)g_xw;
        int i = 0;
        for (; i + 4 <= n; i += 4){
            size_t r0 = ((size_t)srel[w][i+0]*NN + ssrc[w][i+0])*64;
            size_t r1 = ((size_t)srel[w][i+1]*NN + ssrc[w][i+1])*64;
            size_t r2 = ((size_t)srel[w][i+2]*NN + ssrc[w][i+2])*64;
            size_t r3 = ((size_t)srel[w][i+3]*NN + ssrc[w][i+3])*64;
            float4 x0 = xw4[r0 + lane],      x1 = xw4[r1 + lane];
            float4 x2 = xw4[r2 + lane],      x3 = xw4[r3 + lane];
            float4 y0 = xw4[r0 + 32 + lane], y1 = xw4[r1 + 32 + lane];
            float4 y2 = xw4[r2 + 32 + lane], y3 = xw4[r3 + 32 + lane];
            float w0a = sl[w][i+0][h0], w1a = sl[w][i+1][h0];
            float w2a = sl[w][i+2][h0], w3a = sl[w][i+3][h0];
            float w0b = sl[w][i+0][h1], w1b = sl[w][i+1][h1];
            float w2b = sl[w][i+2][h1], w3b = sl[w][i+3][h1];
            acc0a.x += w0a*x0.x; acc0a.y += w0a*x0.y; acc0a.z += w0a*x0.z; acc0a.w += w0a*x0.w;
            acc0b.x += w1a*x1.x; acc0b.y += w1a*x1.y; acc0b.z += w1a*x1.z; acc0b.w += w1a*x1.w;
            acc0c.x += w2a*x2.x; acc0c.y += w2a*x2.y; acc0c.z += w2a*x2.z; acc0c.w += w2a*x2.w;
            acc0d.x += w3a*x3.x; acc0d.y += w3a*x3.y; acc0d.z += w3a*x3.z; acc0d.w += w3a*x3.w;
            acc1a.x += w0b*y0.x; acc1a.y += w0b*y0.y; acc1a.z += w0b*y0.z; acc1a.w += w0b*y0.w;
            acc1b.x += w1b*y1.x; acc1b.y += w1b*y1.y; acc1b.z += w1b*y1.z; acc1b.w += w1b*y1.w;
            acc1c.x += w2b*y2.x; acc1c.y += w2b*y2.y; acc1c.z += w2b*y2.z; acc1c.w += w2b*y2.w;
            acc1d.x += w3b*y3.x; acc1d.y += w3b*y3.y; acc1d.z += w3b*y3.z; acc1d.w += w3b*y3.w;
        }
        for (; i < n; i++){
            size_t r0 = ((size_t)srel[w][i]*NN + ssrc[w][i])*64;
            float4 x0 = xw4[r0 + lane];
            float4 y0 = xw4[r0 + 32 + lane];
            float w0a = sl[w][i][h0], w0b = sl[w][i][h1];
            acc0a.x += w0a*x0.x; acc0a.y += w0a*x0.y; acc0a.z += w0a*x0.z; acc0a.w += w0a*x0.w;
            acc1a.x += w0b*y0.x; acc1a.y += w0b*y0.y; acc1a.z += w0b*y0.z; acc1a.w += w0b*y0.w;
        }
        __syncwarp();
    }

    float inv0 = 1.f / fmaxf(ssum[h0], 1e-16f);
    float inv1 = 1.f / fmaxf(ssum[h1], 1e-16f);
    float4 v0, v1;
    v0.x = ((acc0a.x+acc0b.x) + (acc0c.x+acc0d.x))*inv0;
    v0.y = ((acc0a.y+acc0b.y) + (acc0c.y+acc0d.y))*inv0;
    v0.z = ((acc0a.z+acc0b.z) + (acc0c.z+acc0d.z))*inv0;
    v0.w = ((acc0a.w+acc0b.w) + (acc0c.w+acc0d.w))*inv0;
    v1.x = ((acc1a.x+acc1b.x) + (acc1c.x+acc1d.x))*inv1;
    v1.y = ((acc1a.y+acc1b.y) + (acc1c.y+acc1d.y))*inv1;
    v1.z = ((acc1a.z+acc1b.z) + (acc1c.z+acc1d.z))*inv1;
    v1.w = ((acc1a.w+acc1b.w) + (acc1c.w+acc1d.w))*inv1;
    const float4* b4 = (const float4*)bias;
    float4 bb0 = b4[lane], bb1 = b4[32 + lane];
    v0.x += bb0.x; v0.y += bb0.y; v0.z += bb0.z; v0.w += bb0.w;
    v1.x += bb1.x; v1.y += bb1.y; v1.z += bb1.z; v1.w += bb1.w;
    if (skip){
        const float4* s4 = (const float4*)(skip + (size_t)d*HD);
        float4 sk0 = s4[lane], sk1 = s4[32 + lane];
        v0.x += sk0.x; v0.y += sk0.y; v0.z += sk0.z; v0.w += sk0.w;
        v1.x += sk1.x; v1.y += sk1.y; v1.z += sk1.z; v1.w += sk1.w;
    }
    v0.x = lrelu01(v0.x); v0.y = lrelu01(v0.y); v0.z = lrelu01(v0.z); v0.w = lrelu01(v0.w);
    v1.x = lrelu01(v1.x); v1.y = lrelu01(v1.y); v1.z = lrelu01(v1.z); v1.w = lrelu01(v1.w);
    float4* o4 = (float4*)(out + (size_t)d*HD);
    o4[lane]      = v0;
    o4[32 + lane] = v1;
    if (oh){
        bf16 h, l;
        size_t ob = (size_t)d*HD + lane*4;
        float vv[8] = {v0.x,v0.y,v0.z,v0.w, v1.x,v1.y,v1.z,v1.w};
        #pragma unroll
        for (int j = 0; j < 4; j++){
            split2(vv[j], h, l);   oh[ob + j]       = h; ol[ob + j]       = l;
            split2(vv[4+j], h, l); oh[ob + 128 + j] = h; ol[ob + 128 + j] = l;
        }
    }
}

// ---------------- host ----------------
template<typename T>
static T* sym(const void* s){ void* p = nullptr; cudaGetSymbolAddress(&p, s); return (T*)p; }

extern "C" void kernel_launch(void* const* d_in, const int* in_sizes, int n_in,
                              void* d_out, int out_size)
{
    int iKG, iCCLE, iNID, iEI, iET, iCW1, iCB1, iCW2, iCB2,
        iW1, iQ1, iK1, iB1, iW2, iQ2, iK2, iB2, iSW1, iSB1, iSW2, iSB2;
    if (in_sizes[2] == NN){
        iKG=0; iCCLE=1; iNID=2; iEI=3; iET=4;
        iCW1=5; iCB1=6; iCW2=7; iCB2=8;
        iW1=9; iQ1=10; iK1=11; iB1=12;
        iW2=13; iQ2=14; iK2=15; iB2=16;
        iSW1=17; iSB1=18; iSW2=19; iSB2=20;
    } else {
        iKG=0; iCCLE=1;
        iCW1=2; iCB1=3; iCW2=4; iCB2=5;
        iW1=6; iQ1=7; iK1=8; iB1=9;
        iW2=10; iQ2=11; iK2=12; iB2=13;
        iSW1=14; iSB1=15; iSW2=16; iSB2=17;
        iNID=18; iEI=19; iET=20;
    }
    const float* kg   = (const float*)d_in[iKG];
    const float* ccle = (const float*)d_in[iCCLE];
    const int*   nid  = (const int*)  d_in[iNID];
    const int*   ei   = (const int*)  d_in[iEI];
    const int*   et   = (const int*)  d_in[iET];
    const int*   src  = ei;
    const int*   dst  = ei + EE;
    const float* cw1 = (const float*)d_in[iCW1]; const float* cb1 = (const float*)d_in[iCB1];
    const float* cw2 = (const float*)d_in[iCW2]; const float* cb2 = (const float*)d_in[iCB2];
    const float* w1  = (const float*)d_in[iW1];  const float* q1  = (const float*)d_in[iQ1];
    const float* k1  = (const float*)d_in[iK1];  const float* b1  = (const float*)d_in[iB1];
    const float* w2  = (const float*)d_in[iW2];  const float* q2  = (const float*)d_in[iQ2];
    const float* k2  = (const float*)d_in[iK2];  const float* b2  = (const float*)d_in[iB2];
    const float* sw1 = (const float*)d_in[iSW1]; const float* sb1 = (const float*)d_in[iSB1];
    const float* sw2 = (const float*)d_in[iSW2]; const float* sb2 = (const float*)d_in[iSB2];

    float* pxin = sym<float>(g_xin);  float* pxw  = sym<float>(g_xw);
    float* ps   = sym<float>(g_s);    float* pwqk = sym<float>(g_wqk);
    float* px1  = sym<float>(g_x1);   float* pskp = sym<float>(g_skp);
    bf16* pxinh = sym<bf16>(g_xinh);  bf16* pxinl = sym<bf16>(g_xinl);
    bf16* px1h  = sym<bf16>(g_x1h);   bf16* px1l  = sym<bf16>(g_x1l);
    bf16* phsh  = sym<bf16>(g_hsh);   bf16* phsl  = sym<bf16>(g_hsl);
    bf16* pw1h  = sym<bf16>(g_w1h);   bf16* pw1l  = sym<bf16>(g_w1l);
    bf16* pw2h  = sym<bf16>(g_w2h);   bf16* pw2l  = sym<bf16>(g_w2l);
    bf16* psw1h = sym<bf16>(g_sw1h);  bf16* psw1l = sym<bf16>(g_sw1l);
    bf16* psw2h = sym<bf16>(g_sw2h);  bf16* psw2l = sym<bf16>(g_sw2l);

    const int SMEM_HM = 3*32768;
    cudaFuncSetAttribute(hmma_gemm<0>, cudaFuncAttributeMaxDynamicSharedMemorySize, SMEM_HM);
    cudaFuncSetAttribute(hmma_gemm<1>, cudaFuncAttributeMaxDynamicSharedMemorySize, SMEM_HM);
    cudaFuncSetAttribute(hmma_gemm<2>, cudaFuncAttributeMaxDynamicSharedMemorySize, SMEM_HM);

    static cudaStream_t sS = nullptr;
    static cudaEvent_t evFork, evW1, evW2, evXin, evPre1, evSkip, evX1, evPre2;
    if (!sS){
        cudaStreamCreateWithFlags(&sS, cudaStreamNonBlocking);
        cudaEventCreateWithFlags(&evFork, cudaEventDisableTiming);
        cudaEventCreateWithFlags(&evW1,   cudaEventDisableTiming);
        cudaEventCreateWithFlags(&evW2,   cudaEventDisableTiming);
        cudaEventCreateWithFlags(&evXin,  cudaEventDisableTiming);
        cudaEventCreateWithFlags(&evPre1, cudaEventDisableTiming);
        cudaEventCreateWithFlags(&evSkip, cudaEventDisableTiming);
        cudaEventCreateWithFlags(&evX1,   cudaEventDisableTiming);
        cudaEventCreateWithFlags(&evPre2, cudaEventDisableTiming);
    }

    const int gM  = (NN + 127)/128;   // 157
    const int gM64= (NN + 63)/64;
    const int gE  = (EE + 255)/256;
    const int gEdge = (NN + 7)/8;     // 2500
    dim3 tb(32, 8);

    // ---- fork side stream ----
    cudaEventRecord(evFork, 0);
    cudaStreamWaitEvent(sS, evFork, 0);

    // main: critical path (hmma L1 at launch slot #4 for ncu)
    build_xin<<<NN, 128>>>(kg, ccle, nid, cw1, cb1, cw2, cb2);           // 1
    cudaEventRecord(evXin, 0);
    splitW<<<dim3(8,8,RR), tb, 0, sS>>>(w1, pw1h, pw1l);                 // 2
    cudaEventRecord(evW1, sS);
    make_wqk<<<64, 256, 0, sS>>>(w1, q1, k1);                            // 3
    cudaStreamWaitEvent(0, evW1, 0);
    hmma_gemm<0><<<dim3(gM,2,RR), 256, SMEM_HM>>>(pxinh, pxinl, pw1h, pw1l,
                                                  pxw, nullptr, nullptr, NN, nullptr,
                                                  (size_t)65536, (size_t)NN*HD);  // 4
    // side: remaining prep + CSR + skip chain
    splitW<<<dim3(8,8,RR), tb, 0, sS>>>(w2, pw2h, pw2l);
    cudaEventRecord(evW2, sS);
    zero_deg<<<(NN+255)/256, 256, 0, sS>>>();
    hist<<<gE, 256, 0, sS>>>(dst);
    scan_rowptr<<<1, 1024, 0, sS>>>();
    scatter<<<gE, 256, 0, sS>>>(dst);
    cudaStreamWaitEvent(sS, evXin, 0);
    gemm_k256_n64<<<gM64, 256, 0, sS>>>(pxin, pwqk, ps, NN);
    cudaEventRecord(evPre1, sS);
    make_wqk<<<64, 256, 0, sS>>>(w2, q2, k2);
    splitW<<<dim3(8,8,1), tb, 0, sS>>>(sw1, psw1h, psw1l);
    splitW<<<dim3(8,8,1), tb, 0, sS>>>(sw2, psw2h, psw2l);
    hmma_gemm<1><<<dim3(gM,2,1), 256, SMEM_HM, sS>>>(pxinh, pxinl, psw1h, psw1l,
                                                     nullptr, phsh, phsl, NN, sb1, 0, 0);
    hmma_gemm<2><<<dim3(gM,2,1), 256, SMEM_HM, sS>>>(phsh, phsl, psw2h, psw2l,
                                                     pskp, nullptr, nullptr, NN, sb2, 0, 0);
    cudaEventRecord(evSkip, sS);

    // main: edge L1 (warp-per-dst)
    cudaStreamWaitEvent(0, evPre1, 0);
    edge_fused<<<gEdge, 256>>>(src, et, b1, nullptr, px1, px1h, px1l);
    cudaEventRecord(evX1, 0);

    // side: layer-2 projection
    cudaStreamWaitEvent(sS, evX1, 0);
    gemm_k256_n64<<<gM64, 256, 0, sS>>>(px1, pwqk, ps, NN);
    cudaEventRecord(evPre2, sS);

    // main: layer-2 GEMM + final edge
    cudaStreamWaitEvent(0, evW2, 0);
    hmma_gemm<0><<<dim3(gM,2,RR), 256, SMEM_HM>>>(px1h, px1l, pw2h, pw2l,
                                                  pxw, nullptr, nullptr, NN, nullptr,
                                                  (size_t)65536, (size_t)NN*HD);
    cudaStreamWaitEvent(0, evSkip, 0);
    cudaStreamWaitEvent(0, evPre2, 0);
    edge_fused<<<gEdge, 256>>>(src, et, b2, pskp, (float*)d_out, nullptr, nullptr);
}

// round 11
// speedup vs baseline: 1.0642x; 1.0642x over previous
#include <cuda_runtime.h>
#include <cuda_bf16.h>
#include <cuda_fp16.h>
#include <cstdint>
#include <cstddef>

#define NN   20000
#define EE   320000
#define RR   8
#define HH   4
#define HD   256

typedef __nv_bfloat16 bf16;

// ---------------- device scratch ----------------
__device__ float  g_xin [(size_t)NN*HD];
__device__ __half g_xwh [(size_t)RR*NN*HD];   // fp16 xw table (82 MB)
__device__ float  g_s   [(size_t)NN*64];
__device__ float  g_wqk [256*64];
__device__ float  g_x1  [(size_t)NN*HD];
__device__ float  g_skp [(size_t)NN*HD];
__device__ bf16   g_xinh[(size_t)NN*HD];
__device__ bf16   g_xinl[(size_t)NN*HD];
__device__ bf16   g_x1h [(size_t)NN*HD];
__device__ bf16   g_x1l [(size_t)NN*HD];
__device__ bf16   g_hsh [(size_t)NN*HD];
__device__ bf16   g_hsl [(size_t)NN*HD];
__device__ bf16   g_w1h [(size_t)RR*65536];
__device__ bf16   g_w1l [(size_t)RR*65536];
__device__ bf16   g_w2h [(size_t)RR*65536];
__device__ bf16   g_w2l [(size_t)RR*65536];
__device__ bf16   g_sw1h[65536];
__device__ bf16   g_sw1l[65536];
__device__ bf16   g_sw2h[65536];
__device__ bf16   g_sw2l[65536];
__device__ int g_deg[NN], g_rowptr[NN], g_cur[NN], g_eid[EE];

__device__ __forceinline__ float lrelu01(float v){ return v > 0.f ? v : 0.01f*v; }

__device__ __forceinline__ uint32_t smem_u32(const void* p){
    uint32_t a;
    asm("{ .reg .u64 t; cvta.to.shared.u64 t, %1; cvt.u32.u64 %0, t; }" : "=r"(a) : "l"(p));
    return a;
}
__device__ __forceinline__ void ldsm_x4(uint32_t* r, uint32_t addr){
    asm volatile("ldmatrix.sync.aligned.m8n8.x4.shared.b16 {%0,%1,%2,%3}, [%4];"
        : "=r"(r[0]), "=r"(r[1]), "=r"(r[2]), "=r"(r[3]) : "r"(addr));
}
__device__ __forceinline__ void mma16816(float* d, const uint32_t* a, const uint32_t* b){
    asm volatile("mma.sync.aligned.m16n8k16.row.col.f32.bf16.bf16.f32 "
        "{%0,%1,%2,%3}, {%4,%5,%6,%7}, {%8,%9}, {%0,%1,%2,%3};"
        : "+f"(d[0]), "+f"(d[1]), "+f"(d[2]), "+f"(d[3])
        : "r"(a[0]), "r"(a[1]), "r"(a[2]), "r"(a[3]), "r"(b[0]), "r"(b[1]));
}
__device__ __forceinline__ void cp_async16(uint32_t saddr, const void* g, uint32_t srcsz){
    asm volatile("cp.async.cg.shared.global [%0], [%1], 16, %2;"
                 :: "r"(saddr), "l"(g), "r"(srcsz) : "memory");
}
#define CP_COMMIT() asm volatile("cp.async.commit_group;" ::: "memory")
#define CP_WAIT1()  asm volatile("cp.async.wait_group 1;" ::: "memory")
#define CP_WAIT0()  asm volatile("cp.async.wait_group 0;" ::: "memory")

__device__ __forceinline__ void split2(float v, bf16& h, bf16& l){
    h = __float2bfloat16(v);
    l = __float2bfloat16(v - __bfloat162float(h));
}

__device__ __forceinline__ uint32_t swz(int row, uint32_t colB){
    return (uint32_t)(row*64) + (colB ^ (uint32_t)((row & 6) << 3));
}

// ---------------- x_in build + splits ----------------
__global__ void build_xin(const float* __restrict__ kg, const float* __restrict__ ccle,
                          const int* __restrict__ nid,
                          const float* __restrict__ cw1, const float* __restrict__ cb1,
                          const float* __restrict__ cw2, const float* __restrict__ cb2)
{
    int i = blockIdx.x;
    int t = threadIdx.x;               // 128
    int nd = nid[i];
    __shared__ float c4[4];
    __shared__ float hdn[32];
    if (t < 4) c4[t] = ccle[(size_t)nd*4 + t];
    float v0 = kg[(size_t)nd*128 + t];
    g_xin[(size_t)i*HD + t] = v0;
    bf16 h, l; split2(v0, h, l);
    g_xinh[(size_t)i*HD + t] = h; g_xinl[(size_t)i*HD + t] = l;
    __syncthreads();
    if (t < 32){
        float a = cb1[t];
        #pragma unroll
        for (int j = 0; j < 4; j++) a += c4[j]*cw1[j*32 + t];
        hdn[t] = lrelu01(a);
    }
    __syncthreads();
    float o = cb2[t];
    #pragma unroll 8
    for (int j = 0; j < 32; j++) o += hdn[j]*cw2[j*128 + t];
    g_xin[(size_t)i*HD + 128 + t] = o;
    split2(o, h, l);
    g_xinh[(size_t)i*HD + 128 + t] = h; g_xinl[(size_t)i*HD + 128 + t] = l;
}

// ---------------- W split-transpose ----------------
__global__ void splitW(const float* __restrict__ w, bf16* __restrict__ oh, bf16* __restrict__ ol)
{
    __shared__ float tile[32][33];
    int z = blockIdx.z;
    const float* wz = w + (size_t)z*65536;
    int tx = threadIdx.x, ty = threadIdx.y;   // 32x8
    int k0 = blockIdx.x*32, n0 = blockIdx.y*32;
    #pragma unroll
    for (int i = ty; i < 32; i += 8)
        tile[i][tx] = wz[(size_t)(k0+i)*256 + n0 + tx];
    __syncthreads();
    #pragma unroll
    for (int i = ty; i < 32; i += 8){
        float v = tile[tx][i];
        bf16 h, l; split2(v, h, l);
        size_t o = (size_t)z*65536 + (size_t)(n0+i)*256 + k0 + tx;
        oh[o] = h; ol[o] = l;
    }
}

// ---------------- 3-stage cp.async HMMA GEMM (XOR-swizzled smem) ----------------
// MODE 0: fp16 -> Ch2 (xw table). MODE 1: bias+lrelu -> bf16 splits. MODE 2: bias -> Cf.
__device__ __forceinline__ void hm_load(uint32_t sb, int stg, int kc,
    const bf16* __restrict__ Ah, const bf16* __restrict__ Al,
    const bf16* __restrict__ WhB, const bf16* __restrict__ WlB,
    int row0, int M, int t)
{
    const int kofs = kc*32;
    const uint32_t stBase = sb + (uint32_t)stg*32768u;
    #pragma unroll
    for (int j = 0; j < 2; j++){
        int g   = j*256 + t;
        int row = g >> 2;
        uint32_t cb = (uint32_t)((g & 3) * 16);
        uint32_t so = stBase + swz(row, cb);
        uint32_t ok = (row0 + row < M) ? 16u : 0u;
        size_t go = (size_t)(row0 + row)*256 + kofs + (cb >> 1);
        cp_async16(so,          Ah + go, ok);
        cp_async16(so +  8192u, Al + go, ok);
        size_t gw = (size_t)row*256 + kofs + (cb >> 1);
        cp_async16(so + 16384u, WhB + gw, 16u);
        cp_async16(so + 24576u, WlB + gw, 16u);
    }
}

template<int MODE>
__global__ void __launch_bounds__(256, 2)
hmma_gemm(const bf16* __restrict__ Ah, const bf16* __restrict__ Al,
          const bf16* __restrict__ Wh, const bf16* __restrict__ Wl,
          float* __restrict__ Cf, __half* __restrict__ Ch2,
          bf16* __restrict__ Ch, bf16* __restrict__ Cl,
          int M, const float* __restrict__ bias,
          size_t wStride, size_t cStride)
{
    extern __shared__ char sm[];
    const uint32_t sb = smem_u32(sm);
    const int t = threadIdx.x, lane = t & 31, wid = t >> 5;
    const int wm = wid & 3, wn = wid >> 2;
    const int row0 = blockIdx.x*128;
    const int col0 = blockIdx.y*128;
    const bf16* WhB = Wh + wStride*blockIdx.z + (size_t)col0*256;
    const bf16* WlB = Wl + wStride*blockIdx.z + (size_t)col0*256;

    float acc[2][8][4];
    #pragma unroll
    for (int i = 0; i < 2; i++)
        #pragma unroll
        for (int j = 0; j < 8; j++)
            #pragma unroll
            for (int q = 0; q < 4; q++) acc[i][j][q] = 0.f;

    const int ar  = lane & 15, ac8 = lane >> 4;
    const int bnl = (lane & 7) + ((lane >> 4) << 3);
    const int bkh = (lane >> 3) & 1;

    hm_load(sb, 0, 0, Ah, Al, WhB, WlB, row0, M, t); CP_COMMIT();
    hm_load(sb, 1, 1, Ah, Al, WhB, WlB, row0, M, t); CP_COMMIT();

    int stg = 0, ldstg = 2;
    for (int kc = 0; kc < 8; kc++){
        if (kc < 7) CP_WAIT1(); else CP_WAIT0();
        __syncthreads();
        if (kc < 6){
            hm_load(sb, ldstg, kc+2, Ah, Al, WhB, WlB, row0, M, t);
            CP_COMMIT();
            if (++ldstg == 3) ldstg = 0;
        }

        const uint32_t stBase = sb + (uint32_t)stg*32768u;
        #pragma unroll
        for (int ks = 0; ks < 2; ks++){
            uint32_t a_h[2][4], a_l[2][4], bw[4][4];
            const uint32_t acol = (uint32_t)(ks*32 + ac8*16);
            #pragma unroll
            for (int i = 0; i < 2; i++){
                int row = wm*32 + i*16 + ar;
                uint32_t addr = stBase + swz(row, acol);
                ldsm_x4(a_h[i], addr);
                ldsm_x4(a_l[i], addr + 8192u);
            }
            const uint32_t bcol = (uint32_t)(ks*32 + bkh*16);
            #pragma unroll
            for (int qd = 0; qd < 4; qd++){
                int row = wn*64 + qd*16 + bnl;
                ldsm_x4(bw[qd], stBase + 16384u + swz(row, bcol));
            }
            #pragma unroll
            for (int i = 0; i < 2; i++)
                #pragma unroll
                for (int j = 0; j < 8; j++)
                    mma16816(acc[i][j], a_h[i], &bw[j>>1][(j&1)*2]);
            #pragma unroll
            for (int i = 0; i < 2; i++)
                #pragma unroll
                for (int j = 0; j < 8; j++)
                    mma16816(acc[i][j], a_l[i], &bw[j>>1][(j&1)*2]);
            #pragma unroll
            for (int qd = 0; qd < 4; qd++){
                int row = wn*64 + qd*16 + bnl;
                ldsm_x4(bw[qd], stBase + 24576u + swz(row, bcol));
            }
            #pragma unroll
            for (int i = 0; i < 2; i++)
                #pragma unroll
                for (int j = 0; j < 8; j++)
                    mma16816(acc[i][j], a_h[i], &bw[j>>1][(j&1)*2]);
        }
        if (++stg == 3) stg = 0;
    }

    const int cr = lane >> 2, cc = (lane & 3)*2;
    #pragma unroll
    for (int i = 0; i < 2; i++){
        #pragma unroll
        for (int rr = 0; rr < 2; rr++){
            int grow = row0 + wm*32 + i*16 + rr*8 + cr;
            if (grow >= M) continue;
            #pragma unroll
            for (int j = 0; j < 8; j++){
                int gcol = col0 + wn*64 + j*8 + cc;
                float v0 = acc[i][j][rr*2+0];
                float v1 = acc[i][j][rr*2+1];
                if (MODE == 0){
                    *(__half2*)(Ch2 + cStride*blockIdx.z + (size_t)grow*256 + gcol) =
                        __floats2half2_rn(v0, v1);
                } else if (MODE == 1){
                    v0 = lrelu01(v0 + bias[gcol]);
                    v1 = lrelu01(v1 + bias[gcol+1]);
                    bf16 h0, l0, h1, l1;
                    split2(v0, h0, l0); split2(v1, h1, l1);
                    Ch[(size_t)grow*256 + gcol]   = h0; Ch[(size_t)grow*256 + gcol+1] = h1;
                    Cl[(size_t)grow*256 + gcol]   = l0; Cl[(size_t)grow*256 + gcol+1] = l1;
                } else {
                    float2 f; f.x = v0 + bias[gcol]; f.y = v1 + bias[gcol+1];
                    *(float2*)(Cf + (size_t)grow*256 + gcol) = f;
                }
            }
        }
    }
}

// ---------------- wqk fold + small projection GEMM ----------------
__global__ void make_wqk(const float* __restrict__ w, const float* __restrict__ q,
                         const float* __restrict__ km)
{
    int idx = blockIdx.x*blockDim.x + threadIdx.x;
    int kk  = idx >> 6;
    int j   = idx & 63;
    int isK = (j >= 32);
    int rh  = isK ? j - 32 : j;
    int r   = rh >> 2, h = rh & 3;
    const float* wm = w + ((size_t)r*256 + kk)*256;
    const float* qm = isK ? km : q;
    float a = 0.f;
    #pragma unroll 8
    for (int o = 0; o < 256; o++) a += wm[o]*qm[o*4 + h];
    g_wqk[kk*64 + j] = a;
}

__global__ void gemm_k256_n64(const float* __restrict__ A, const float* __restrict__ W,
                              float* __restrict__ C, int M)
{
    constexpr int BM = 64, BK = 16, BN = 64;
    constexpr int TN = 4, TM = 4;
    __shared__ float As[BK][BM + 4];
    __shared__ float Ws[BK][BN];
    int row0 = blockIdx.x*BM;
    int t  = threadIdx.x;
    int tx = t & 15, ty = t >> 4;
    float acc[TM][TN] = {};
    int aRow = t >> 2;
    int aK4  = (t & 3) * 4;
    for (int k0 = 0; k0 < 256; k0 += BK){
        float4 av = make_float4(0.f,0.f,0.f,0.f);
        int gr = row0 + aRow;
        if (gr < M) av = *(const float4*)(A + (size_t)gr*256 + k0 + aK4);
        As[aK4+0][aRow] = av.x; As[aK4+1][aRow] = av.y;
        As[aK4+2][aRow] = av.z; As[aK4+3][aRow] = av.w;
        {
            int kk = t / 16, j4 = (t % 16) * 4;
            *(float4*)&Ws[kk][j4] = *(const float4*)(W + (size_t)(k0+kk)*64 + j4);
        }
        __syncthreads();
        #pragma unroll
        for (int kk = 0; kk < BK; kk++){
            float a[TM], bb[TN];
            #pragma unroll
            for (int i = 0; i < TM; i++) a[i] = As[kk][ty*TM + i];
            #pragma unroll
            for (int j = 0; j < TN; j++) bb[j] = Ws[kk][tx*TN + j];
            #pragma unroll
            for (int i = 0; i < TM; i++)
                #pragma unroll
                for (int j = 0; j < TN; j++) acc[i][j] += a[i]*bb[j];
        }
        __syncthreads();
    }
    #pragma unroll
    for (int i = 0; i < TM; i++){
        int gr = row0 + ty*TM + i;
        if (gr >= M) continue;
        #pragma unroll
        for (int j = 0; j < TN; j++)
            C[(size_t)gr*64 + tx*TN + j] = acc[i][j];
    }
}

// ---------------- CSR build ----------------
__global__ void zero_deg(){
    int i = blockIdx.x*blockDim.x + threadIdx.x;
    if (i < NN) g_deg[i] = 0;
}
__global__ void hist(const int* __restrict__ dst){
    int e = blockIdx.x*blockDim.x + threadIdx.x;
    if (e < EE) atomicAdd(&g_deg[dst[e]], 1);
}
__global__ void scan_rowptr(){
    __shared__ int wsum[32];
    int t = threadIdx.x, lane = t & 31, wid = t >> 5;
    int beg = t*20, end = beg + 20; if (end > NN) end = NN;
    int s = 0;
    for (int i = beg; i < end; i++) s += g_deg[i];
    int v = s;
    #pragma unroll
    for (int o = 1; o < 32; o <<= 1){
        int u = __shfl_up_sync(0xffffffffu, v, o);
        if (lane >= o) v += u;
    }
    if (lane == 31) wsum[wid] = v;
    __syncthreads();
    if (wid == 0){
        int w = wsum[lane];
        #pragma unroll
        for (int o = 1; o < 32; o <<= 1){
            int u = __shfl_up_sync(0xffffffffu, w, o);
            if (lane >= o) w += u;
        }
        wsum[lane] = w;
    }
    __syncthreads();
    int run = v - s + (wid ? wsum[wid-1] : 0);
    for (int i = beg; i < end; i++){
        g_rowptr[i] = run;
        g_cur[i]    = run;
        run += g_deg[i];
    }
}
__global__ void scatter(const int* __restrict__ dst){
    int e = blockIdx.x*blockDim.x + threadIdx.x;
    if (e >= EE) return;
    int slot = atomicAdd(&g_cur[dst[e]], 1);
    g_eid[slot] = e;
}

// ---------------- fused per-destination attention + aggregation (fp16 xw) -------------
// 128 threads per dst; thread t owns cols {2t, 2t+1} (one half2), head h = t>>5.
__global__ void edge_fused(const int* __restrict__ src, const int* __restrict__ et,
                           const float* __restrict__ bias,
                           const float* __restrict__ skip,
                           float* __restrict__ out,
                           bf16* __restrict__ oh, bf16* __restrict__ ol)
{
    const int d = blockIdx.x;
    const int t = threadIdx.x;          // 128
    const int wid  = t >> 5, lane = t & 31;
    const int base = g_rowptr[d], deg = g_deg[d];
    const int h = t >> 5;               // head for this thread's column pair

    __shared__ float sl[128][4];
    __shared__ int   ssrc[128];
    __shared__ int   srel[128];
    __shared__ float redm[4][4];
    __shared__ float reds[4][4];

    float2 a[8];
    #pragma unroll
    for (int u = 0; u < 8; u++){ a[u].x = 0.f; a[u].y = 0.f; }
    float m[4], ssum[4];
    #pragma unroll
    for (int hh = 0; hh < 4; hh++){ m[hh] = -1e30f; ssum[hh] = 0.f; }

    const __half2* xw2 = (const __half2*)g_xwh;

    for (int c0 = 0; c0 < deg; c0 += 128){
        int n = deg - c0; if (n > 128) n = 128;
        float l[4];
        if (t < n){
            int e = g_eid[base + c0 + t];
            int s = src[e], r = et[e];
            ssrc[t] = s; srel[t] = r;
            const float* qv = g_s + (size_t)d*64 + r*4;
            const float* kv = g_s + (size_t)s*64 + 32 + r*4;
            #pragma unroll
            for (int hh = 0; hh < 4; hh++){
                float v = qv[hh] + kv[hh];
                l[hh] = v > 0.f ? v : 0.2f*v;
            }
        } else {
            #pragma unroll
            for (int hh = 0; hh < 4; hh++) l[hh] = -1e30f;
        }
        float lm[4];
        #pragma unroll
        for (int hh = 0; hh < 4; hh++){
            float v = l[hh];
            #pragma unroll
            for (int o = 16; o; o >>= 1) v = fmaxf(v, __shfl_xor_sync(0xffffffffu, v, o));
            lm[hh] = v;
        }
        if (lane == 0){
            #pragma unroll
            for (int hh = 0; hh < 4; hh++) redm[wid][hh] = lm[hh];
        }
        __syncthreads();
        float newm[4], scale[4];
        #pragma unroll
        for (int hh = 0; hh < 4; hh++){
            float cm = fmaxf(fmaxf(redm[0][hh], redm[1][hh]), fmaxf(redm[2][hh], redm[3][hh]));
            newm[hh]  = fmaxf(m[hh], cm);
            scale[hh] = __expf(m[hh] - newm[hh]);
            m[hh]     = newm[hh];
            ssum[hh] *= scale[hh];
        }
        float sc = scale[h];
        #pragma unroll
        for (int u = 0; u < 8; u++){ a[u].x *= sc; a[u].y *= sc; }
        float es[4];
        #pragma unroll
        for (int hh = 0; hh < 4; hh++){
            float e = (t < n) ? __expf(l[hh] - newm[hh]) : 0.f;
            sl[t][hh] = e;
            #pragma unroll
            for (int o = 16; o; o >>= 1) e += __shfl_xor_sync(0xffffffffu, e, o);
            es[hh] = e;
        }
        if (lane == 0){
            #pragma unroll
            for (int hh = 0; hh < 4; hh++) reds[wid][hh] = es[hh];
        }
        __syncthreads();
        #pragma unroll
        for (int hh = 0; hh < 4; hh++)
            ssum[hh] += reds[0][hh] + reds[1][hh] + reds[2][hh] + reds[3][hh];

        // message accumulation: one half2 per edge per thread, 8-deep unroll
        int i = 0;
        for (; i + 8 <= n; i += 8){
            float2 xv[8];
            #pragma unroll
            for (int u = 0; u < 8; u++){
                size_t row = ((size_t)srel[i+u]*NN + ssrc[i+u])*128;
                xv[u] = __half22float2(xw2[row + t]);
            }
            #pragma unroll
            for (int u = 0; u < 8; u++){
                float ww = sl[i+u][h];
                a[u].x += ww*xv[u].x;
                a[u].y += ww*xv[u].y;
            }
        }
        for (; i < n; i++){
            size_t row = ((size_t)srel[i]*NN + ssrc[i])*128;
            float2 xv = __half22float2(xw2[row + t]);
            float ww = sl[i][h];
            a[0].x += ww*xv.x;
            a[0].y += ww*xv.y;
        }
        __syncthreads();
    }

    float inv = 1.f / fmaxf(ssum[h], 1e-16f);
    float v0 = (((a[0].x+a[1].x) + (a[2].x+a[3].x)) + ((a[4].x+a[5].x) + (a[6].x+a[7].x)))*inv;
    float v1 = (((a[0].y+a[1].y) + (a[2].y+a[3].y)) + ((a[4].y+a[5].y) + (a[6].y+a[7].y)))*inv;
    int c0 = t*2;
    v0 += bias[c0];
    v1 += bias[c0+1];
    if (skip){
        v0 += skip[(size_t)d*HD + c0];
        v1 += skip[(size_t)d*HD + c0 + 1];
    }
    v0 = lrelu01(v0); v1 = lrelu01(v1);
    float2 vv; vv.x = v0; vv.y = v1;
    *(float2*)(out + (size_t)d*HD + c0) = vv;
    if (oh){
        bf16 hh, ll;
        split2(v0, hh, ll); oh[(size_t)d*HD + c0]     = hh; ol[(size_t)d*HD + c0]     = ll;
        split2(v1, hh, ll); oh[(size_t)d*HD + c0 + 1] = hh; ol[(size_t)d*HD + c0 + 1] = ll;
    }
}

// ---------------- host ----------------
template<typename T>
static T* sym(const void* s){ void* p = nullptr; cudaGetSymbolAddress(&p, s); return (T*)p; }

extern "C" void kernel_launch(void* const* d_in, const int* in_sizes, int n_in,
                              void* d_out, int out_size)
{
    int iKG, iCCLE, iNID, iEI, iET, iCW1, iCB1, iCW2, iCB2,
        iW1, iQ1, iK1, iB1, iW2, iQ2, iK2, iB2, iSW1, iSB1, iSW2, iSB2;
    if (in_sizes[2] == NN){
        iKG=0; iCCLE=1; iNID=2; iEI=3; iET=4;
        iCW1=5; iCB1=6; iCW2=7; iCB2=8;
        iW1=9; iQ1=10; iK1=11; iB1=12;
        iW2=13; iQ2=14; iK2=15; iB2=16;
        iSW1=17; iSB1=18; iSW2=19; iSB2=20;
    } else {
        iKG=0; iCCLE=1;
        iCW1=2; iCB1=3; iCW2=4; iCB2=5;
        iW1=6; iQ1=7; iK1=8; iB1=9;
        iW2=10; iQ2=11; iK2=12; iB2=13;
        iSW1=14; iSB1=15; iSW2=16; iSB2=17;
        iNID=18; iEI=19; iET=20;
    }
    const float* kg   = (const float*)d_in[iKG];
    const float* ccle = (const float*)d_in[iCCLE];
    const int*   nid  = (const int*)  d_in[iNID];
    const int*   ei   = (const int*)  d_in[iEI];
    const int*   et   = (const int*)  d_in[iET];
    const int*   src  = ei;
    const int*   dst  = ei + EE;
    const float* cw1 = (const float*)d_in[iCW1]; const float* cb1 = (const float*)d_in[iCB1];
    const float* cw2 = (const float*)d_in[iCW2]; const float* cb2 = (const float*)d_in[iCB2];
    const float* w1  = (const float*)d_in[iW1];  const float* q1  = (const float*)d_in[iQ1];
    const float* k1  = (const float*)d_in[iK1];  const float* b1  = (const float*)d_in[iB1];
    const float* w2  = (const float*)d_in[iW2];  const float* q2  = (const float*)d_in[iQ2];
    const float* k2  = (const float*)d_in[iK2];  const float* b2  = (const float*)d_in[iB2];
    const float* sw1 = (const float*)d_in[iSW1]; const float* sb1 = (const float*)d_in[iSB1];
    const float* sw2 = (const float*)d_in[iSW2]; const float* sb2 = (const float*)d_in[iSB2];

    float* pxin  = sym<float>(g_xin);
    __half* pxwh = sym<__half>(g_xwh);
    float* ps    = sym<float>(g_s);    float* pwqk = sym<float>(g_wqk);
    float* px1   = sym<float>(g_x1);   float* pskp = sym<float>(g_skp);
    bf16* pxinh = sym<bf16>(g_xinh);  bf16* pxinl = sym<bf16>(g_xinl);
    bf16* px1h  = sym<bf16>(g_x1h);   bf16* px1l  = sym<bf16>(g_x1l);
    bf16* phsh  = sym<bf16>(g_hsh);   bf16* phsl  = sym<bf16>(g_hsl);
    bf16* pw1h  = sym<bf16>(g_w1h);   bf16* pw1l  = sym<bf16>(g_w1l);
    bf16* pw2h  = sym<bf16>(g_w2h);   bf16* pw2l  = sym<bf16>(g_w2l);
    bf16* psw1h = sym<bf16>(g_sw1h);  bf16* psw1l = sym<bf16>(g_sw1l);
    bf16* psw2h = sym<bf16>(g_sw2h);  bf16* psw2l = sym<bf16>(g_sw2l);

    const int SMEM_HM = 3*32768;
    cudaFuncSetAttribute(hmma_gemm<0>, cudaFuncAttributeMaxDynamicSharedMemorySize, SMEM_HM);
    cudaFuncSetAttribute(hmma_gemm<1>, cudaFuncAttributeMaxDynamicSharedMemorySize, SMEM_HM);
    cudaFuncSetAttribute(hmma_gemm<2>, cudaFuncAttributeMaxDynamicSharedMemorySize, SMEM_HM);

    static cudaStream_t sS = nullptr;
    static cudaEvent_t evFork, evW1, evW2, evXin, evPre1, evSkip, evX1, evPre2;
    if (!sS){
        cudaStreamCreateWithFlags(&sS, cudaStreamNonBlocking);
        cudaEventCreateWithFlags(&evFork, cudaEventDisableTiming);
        cudaEventCreateWithFlags(&evW1,   cudaEventDisableTiming);
        cudaEventCreateWithFlags(&evW2,   cudaEventDisableTiming);
        cudaEventCreateWithFlags(&evXin,  cudaEventDisableTiming);
        cudaEventCreateWithFlags(&evPre1, cudaEventDisableTiming);
        cudaEventCreateWithFlags(&evSkip, cudaEventDisableTiming);
        cudaEventCreateWithFlags(&evX1,   cudaEventDisableTiming);
        cudaEventCreateWithFlags(&evPre2, cudaEventDisableTiming);
    }

    const int gM  = (NN + 127)/128;   // 157
    const int gM64= (NN + 63)/64;
    const int gE  = (EE + 255)/256;
    dim3 tb(32, 8);

    // ---- fork side stream ----
    cudaEventRecord(evFork, 0);
    cudaStreamWaitEvent(sS, evFork, 0);

    // main: critical path (hmma L1 at launch slot #4 for ncu)
    build_xin<<<NN, 128>>>(kg, ccle, nid, cw1, cb1, cw2, cb2);           // 1
    cudaEventRecord(evXin, 0);
    splitW<<<dim3(8,8,RR), tb, 0, sS>>>(w1, pw1h, pw1l);                 // 2
    cudaEventRecord(evW1, sS);
    make_wqk<<<64, 256, 0, sS>>>(w1, q1, k1);                            // 3
    cudaStreamWaitEvent(0, evW1, 0);
    hmma_gemm<0><<<dim3(gM,2,RR), 256, SMEM_HM>>>(pxinh, pxinl, pw1h, pw1l,
                                                  nullptr, pxwh, nullptr, nullptr, NN, nullptr,
                                                  (size_t)65536, (size_t)NN*HD);  // 4
    // side: remaining prep + CSR + skip chain
    splitW<<<dim3(8,8,RR), tb, 0, sS>>>(w2, pw2h, pw2l);
    cudaEventRecord(evW2, sS);
    zero_deg<<<(NN+255)/256, 256, 0, sS>>>();
    hist<<<gE, 256, 0, sS>>>(dst);
    scan_rowptr<<<1, 1024, 0, sS>>>();
    scatter<<<gE, 256, 0, sS>>>(dst);
    cudaStreamWaitEvent(sS, evXin, 0);
    gemm_k256_n64<<<gM64, 256, 0, sS>>>(pxin, pwqk, ps, NN);
    cudaEventRecord(evPre1, sS);
    make_wqk<<<64, 256, 0, sS>>>(w2, q2, k2);
    splitW<<<dim3(8,8,1), tb, 0, sS>>>(sw1, psw1h, psw1l);
    splitW<<<dim3(8,8,1), tb, 0, sS>>>(sw2, psw2h, psw2l);
    hmma_gemm<1><<<dim3(gM,2,1), 256, SMEM_HM, sS>>>(pxinh, pxinl, psw1h, psw1l,
                                                     nullptr, nullptr, phsh, phsl, NN, sb1, 0, 0);
    hmma_gemm<2><<<dim3(gM,2,1), 256, SMEM_HM, sS>>>(phsh, phsl, psw2h, psw2l,
                                                     pskp, nullptr, nullptr, nullptr, NN, sb2, 0, 0);
    cudaEventRecord(evSkip, sS);

    // main: edge L1
    cudaStreamWaitEvent(0, evPre1, 0);
    edge_fused<<<NN, 128>>>(src, et, b1, nullptr, px1, px1h, px1l);
    cudaEventRecord(evX1, 0);

    // side: layer-2 projection
    cudaStreamWaitEvent(sS, evX1, 0);
    gemm_k256_n64<<<gM64, 256, 0, sS>>>(px1, pwqk, ps, NN);
    cudaEventRecord(evPre2, sS);

    // main: layer-2 GEMM + final edge
    cudaStreamWaitEvent(0, evW2, 0);
    hmma_gemm<0><<<dim3(gM,2,RR), 256, SMEM_HM>>>(px1h, px1l, pw2h, pw2l,
                                                  nullptr, pxwh, nullptr, nullptr, NN, nullptr,
                                                  (size_t)65536, (size_t)NN*HD);
    cudaStreamWaitEvent(0, evSkip, 0);
    cudaStreamWaitEvent(0, evPre2, 0);
    edge_fused<<<NN, 128>>>(src, et, b2, pskp, (float*)d_out, nullptr, nullptr);
}

// round 12
// speedup vs baseline: 1.1409x; 1.0721x over previous
#include <cuda_runtime.h>
#include <cuda_bf16.h>
#include <cuda_fp16.h>
#include <cstdint>
#include <cstddef>

#define NN   20000
#define EE   320000
#define RR   8
#define HH   4
#define HD   256

typedef __nv_bfloat16 bf16;

// ---------------- device scratch ----------------
__device__ float  g_xin [(size_t)NN*HD];
__device__ __half g_xwh [(size_t)RR*NN*HD];   // fp16 xw table (82 MB)
__device__ float  g_s   [(size_t)NN*64];
__device__ float  g_wqk [256*64];
__device__ float  g_x1  [(size_t)NN*HD];
__device__ float  g_skp [(size_t)NN*HD];
__device__ bf16   g_xinh[(size_t)NN*HD];
__device__ bf16   g_xinl[(size_t)NN*HD];
__device__ bf16   g_x1h [(size_t)NN*HD];
__device__ bf16   g_x1l [(size_t)NN*HD];
__device__ bf16   g_hsh [(size_t)NN*HD];
__device__ bf16   g_hsl [(size_t)NN*HD];
__device__ bf16   g_w1h [(size_t)RR*65536];
__device__ bf16   g_w1l [(size_t)RR*65536];
__device__ bf16   g_w2h [(size_t)RR*65536];
__device__ bf16   g_w2l [(size_t)RR*65536];
__device__ bf16   g_sw1h[65536];
__device__ bf16   g_sw1l[65536];
__device__ bf16   g_sw2h[65536];
__device__ bf16   g_sw2l[65536];
__device__ int g_deg[NN], g_rowptr[NN], g_cur[NN], g_eid[EE];

__device__ __forceinline__ float lrelu01(float v){ return v > 0.f ? v : 0.01f*v; }

__device__ __forceinline__ uint32_t smem_u32(const void* p){
    uint32_t a;
    asm("{ .reg .u64 t; cvta.to.shared.u64 t, %1; cvt.u32.u64 %0, t; }" : "=r"(a) : "l"(p));
    return a;
}
__device__ __forceinline__ void ldsm_x4(uint32_t* r, uint32_t addr){
    asm volatile("ldmatrix.sync.aligned.m8n8.x4.shared.b16 {%0,%1,%2,%3}, [%4];"
        : "=r"(r[0]), "=r"(r[1]), "=r"(r[2]), "=r"(r[3]) : "r"(addr));
}
__device__ __forceinline__ void mma16816(float* d, const uint32_t* a, const uint32_t* b){
    asm volatile("mma.sync.aligned.m16n8k16.row.col.f32.bf16.bf16.f32 "
        "{%0,%1,%2,%3}, {%4,%5,%6,%7}, {%8,%9}, {%0,%1,%2,%3};"
        : "+f"(d[0]), "+f"(d[1]), "+f"(d[2]), "+f"(d[3])
        : "r"(a[0]), "r"(a[1]), "r"(a[2]), "r"(a[3]), "r"(b[0]), "r"(b[1]));
}
__device__ __forceinline__ void cp_async16(uint32_t saddr, const void* g, uint32_t srcsz){
    asm volatile("cp.async.cg.shared.global [%0], [%1], 16, %2;"
                 :: "r"(saddr), "l"(g), "r"(srcsz) : "memory");
}
#define CP_COMMIT() asm volatile("cp.async.commit_group;" ::: "memory")
#define CP_WAIT1()  asm volatile("cp.async.wait_group 1;" ::: "memory")
#define CP_WAIT0()  asm volatile("cp.async.wait_group 0;" ::: "memory")

__device__ __forceinline__ void split2(float v, bf16& h, bf16& l){
    h = __float2bfloat16(v);
    l = __float2bfloat16(v - __bfloat162float(h));
}

__device__ __forceinline__ uint32_t swz(int row, uint32_t colB){
    return (uint32_t)(row*64) + (colB ^ (uint32_t)((row & 6) << 3));
}

// ---------------- x_in build + splits ----------------
__global__ void build_xin(const float* __restrict__ kg, const float* __restrict__ ccle,
                          const int* __restrict__ nid,
                          const float* __restrict__ cw1, const float* __restrict__ cb1,
                          const float* __restrict__ cw2, const float* __restrict__ cb2)
{
    int i = blockIdx.x;
    int t = threadIdx.x;               // 128
    int nd = nid[i];
    __shared__ float c4[4];
    __shared__ float hdn[32];
    if (t < 4) c4[t] = ccle[(size_t)nd*4 + t];
    float v0 = kg[(size_t)nd*128 + t];
    g_xin[(size_t)i*HD + t] = v0;
    bf16 h, l; split2(v0, h, l);
    g_xinh[(size_t)i*HD + t] = h; g_xinl[(size_t)i*HD + t] = l;
    __syncthreads();
    if (t < 32){
        float a = cb1[t];
        #pragma unroll
        for (int j = 0; j < 4; j++) a += c4[j]*cw1[j*32 + t];
        hdn[t] = lrelu01(a);
    }
    __syncthreads();
    float o = cb2[t];
    #pragma unroll 8
    for (int j = 0; j < 32; j++) o += hdn[j]*cw2[j*128 + t];
    g_xin[(size_t)i*HD + 128 + t] = o;
    split2(o, h, l);
    g_xinh[(size_t)i*HD + 128 + t] = h; g_xinl[(size_t)i*HD + 128 + t] = l;
}

// ---------------- W split-transpose ----------------
__global__ void splitW(const float* __restrict__ w, bf16* __restrict__ oh, bf16* __restrict__ ol)
{
    __shared__ float tile[32][33];
    int z = blockIdx.z;
    const float* wz = w + (size_t)z*65536;
    int tx = threadIdx.x, ty = threadIdx.y;   // 32x8
    int k0 = blockIdx.x*32, n0 = blockIdx.y*32;
    #pragma unroll
    for (int i = ty; i < 32; i += 8)
        tile[i][tx] = wz[(size_t)(k0+i)*256 + n0 + tx];
    __syncthreads();
    #pragma unroll
    for (int i = ty; i < 32; i += 8){
        float v = tile[tx][i];
        bf16 h, l; split2(v, h, l);
        size_t o = (size_t)z*65536 + (size_t)(n0+i)*256 + k0 + tx;
        oh[o] = h; ol[o] = l;
    }
}

// ---------------- 3-stage cp.async HMMA GEMM (XOR-swizzled smem) ----------------
__device__ __forceinline__ void hm_load(uint32_t sb, int stg, int kc,
    const bf16* __restrict__ Ah, const bf16* __restrict__ Al,
    const bf16* __restrict__ WhB, const bf16* __restrict__ WlB,
    int row0, int M, int t)
{
    const int kofs = kc*32;
    const uint32_t stBase = sb + (uint32_t)stg*32768u;
    #pragma unroll
    for (int j = 0; j < 2; j++){
        int g   = j*256 + t;
        int row = g >> 2;
        uint32_t cb = (uint32_t)((g & 3) * 16);
        uint32_t so = stBase + swz(row, cb);
        uint32_t ok = (row0 + row < M) ? 16u : 0u;
        size_t go = (size_t)(row0 + row)*256 + kofs + (cb >> 1);
        cp_async16(so,          Ah + go, ok);
        cp_async16(so +  8192u, Al + go, ok);
        size_t gw = (size_t)row*256 + kofs + (cb >> 1);
        cp_async16(so + 16384u, WhB + gw, 16u);
        cp_async16(so + 24576u, WlB + gw, 16u);
    }
}

template<int MODE>
__global__ void __launch_bounds__(256, 2)
hmma_gemm(const bf16* __restrict__ Ah, const bf16* __restrict__ Al,
          const bf16* __restrict__ Wh, const bf16* __restrict__ Wl,
          float* __restrict__ Cf, __half* __restrict__ Ch2,
          bf16* __restrict__ Ch, bf16* __restrict__ Cl,
          int M, const float* __restrict__ bias,
          size_t wStride, size_t cStride)
{
    extern __shared__ char sm[];
    const uint32_t sb = smem_u32(sm);
    const int t = threadIdx.x, lane = t & 31, wid = t >> 5;
    const int wm = wid & 3, wn = wid >> 2;
    const int row0 = blockIdx.x*128;
    const int col0 = blockIdx.y*128;
    const bf16* WhB = Wh + wStride*blockIdx.z + (size_t)col0*256;
    const bf16* WlB = Wl + wStride*blockIdx.z + (size_t)col0*256;

    float acc[2][8][4];
    #pragma unroll
    for (int i = 0; i < 2; i++)
        #pragma unroll
        for (int j = 0; j < 8; j++)
            #pragma unroll
            for (int q = 0; q < 4; q++) acc[i][j][q] = 0.f;

    const int ar  = lane & 15, ac8 = lane >> 4;
    const int bnl = (lane & 7) + ((lane >> 4) << 3);
    const int bkh = (lane >> 3) & 1;

    hm_load(sb, 0, 0, Ah, Al, WhB, WlB, row0, M, t); CP_COMMIT();
    hm_load(sb, 1, 1, Ah, Al, WhB, WlB, row0, M, t); CP_COMMIT();

    int stg = 0, ldstg = 2;
    for (int kc = 0; kc < 8; kc++){
        if (kc < 7) CP_WAIT1(); else CP_WAIT0();
        __syncthreads();
        if (kc < 6){
            hm_load(sb, ldstg, kc+2, Ah, Al, WhB, WlB, row0, M, t);
            CP_COMMIT();
            if (++ldstg == 3) ldstg = 0;
        }

        const uint32_t stBase = sb + (uint32_t)stg*32768u;
        #pragma unroll
        for (int ks = 0; ks < 2; ks++){
            uint32_t a_h[2][4], a_l[2][4], bw[4][4];
            const uint32_t acol = (uint32_t)(ks*32 + ac8*16);
            #pragma unroll
            for (int i = 0; i < 2; i++){
                int row = wm*32 + i*16 + ar;
                uint32_t addr = stBase + swz(row, acol);
                ldsm_x4(a_h[i], addr);
                ldsm_x4(a_l[i], addr + 8192u);
            }
            const uint32_t bcol = (uint32_t)(ks*32 + bkh*16);
            #pragma unroll
            for (int qd = 0; qd < 4; qd++){
                int row = wn*64 + qd*16 + bnl;
                ldsm_x4(bw[qd], stBase + 16384u + swz(row, bcol));
            }
            #pragma unroll
            for (int i = 0; i < 2; i++)
                #pragma unroll
                for (int j = 0; j < 8; j++)
                    mma16816(acc[i][j], a_h[i], &bw[j>>1][(j&1)*2]);
            #pragma unroll
            for (int i = 0; i < 2; i++)
                #pragma unroll
                for (int j = 0; j < 8; j++)
                    mma16816(acc[i][j], a_l[i], &bw[j>>1][(j&1)*2]);
            #pragma unroll
            for (int qd = 0; qd < 4; qd++){
                int row = wn*64 + qd*16 + bnl;
                ldsm_x4(bw[qd], stBase + 24576u + swz(row, bcol));
            }
            #pragma unroll
            for (int i = 0; i < 2; i++)
                #pragma unroll
                for (int j = 0; j < 8; j++)
                    mma16816(acc[i][j], a_h[i], &bw[j>>1][(j&1)*2]);
        }
        if (++stg == 3) stg = 0;
    }

    const int cr = lane >> 2, cc = (lane & 3)*2;
    #pragma unroll
    for (int i = 0; i < 2; i++){
        #pragma unroll
        for (int rr = 0; rr < 2; rr++){
            int grow = row0 + wm*32 + i*16 + rr*8 + cr;
            if (grow >= M) continue;
            #pragma unroll
            for (int j = 0; j < 8; j++){
                int gcol = col0 + wn*64 + j*8 + cc;
                float v0 = acc[i][j][rr*2+0];
                float v1 = acc[i][j][rr*2+1];
                if (MODE == 0){
                    *(__half2*)(Ch2 + cStride*blockIdx.z + (size_t)grow*256 + gcol) =
                        __floats2half2_rn(v0, v1);
                } else if (MODE == 1){
                    v0 = lrelu01(v0 + bias[gcol]);
                    v1 = lrelu01(v1 + bias[gcol+1]);
                    bf16 h0, l0, h1, l1;
                    split2(v0, h0, l0); split2(v1, h1, l1);
                    Ch[(size_t)grow*256 + gcol]   = h0; Ch[(size_t)grow*256 + gcol+1] = h1;
                    Cl[(size_t)grow*256 + gcol]   = l0; Cl[(size_t)grow*256 + gcol+1] = l1;
                } else {
                    float2 f; f.x = v0 + bias[gcol]; f.y = v1 + bias[gcol+1];
                    *(float2*)(Cf + (size_t)grow*256 + gcol) = f;
                }
            }
        }
    }
}

// ---------------- wqk fold + small projection GEMM ----------------
__global__ void make_wqk(const float* __restrict__ w, const float* __restrict__ q,
                         const float* __restrict__ km)
{
    int idx = blockIdx.x*blockDim.x + threadIdx.x;
    int kk  = idx >> 6;
    int j   = idx & 63;
    int isK = (j >= 32);
    int rh  = isK ? j - 32 : j;
    int r   = rh >> 2, h = rh & 3;
    const float* wm = w + ((size_t)r*256 + kk)*256;
    const float* qm = isK ? km : q;
    float a = 0.f;
    #pragma unroll 8
    for (int o = 0; o < 256; o++) a += wm[o]*qm[o*4 + h];
    g_wqk[kk*64 + j] = a;
}

__global__ void gemm_k256_n64(const float* __restrict__ A, const float* __restrict__ W,
                              float* __restrict__ C, int M)
{
    constexpr int BM = 64, BK = 16, BN = 64;
    constexpr int TN = 4, TM = 4;
    __shared__ float As[BK][BM + 4];
    __shared__ float Ws[BK][BN];
    int row0 = blockIdx.x*BM;
    int t  = threadIdx.x;
    int tx = t & 15, ty = t >> 4;
    float acc[TM][TN] = {};
    int aRow = t >> 2;
    int aK4  = (t & 3) * 4;
    for (int k0 = 0; k0 < 256; k0 += BK){
        float4 av = make_float4(0.f,0.f,0.f,0.f);
        int gr = row0 + aRow;
        if (gr < M) av = *(const float4*)(A + (size_t)gr*256 + k0 + aK4);
        As[aK4+0][aRow] = av.x; As[aK4+1][aRow] = av.y;
        As[aK4+2][aRow] = av.z; As[aK4+3][aRow] = av.w;
        {
            int kk = t / 16, j4 = (t % 16) * 4;
            *(float4*)&Ws[kk][j4] = *(const float4*)(W + (size_t)(k0+kk)*64 + j4);
        }
        __syncthreads();
        #pragma unroll
        for (int kk = 0; kk < BK; kk++){
            float a[TM], bb[TN];
            #pragma unroll
            for (int i = 0; i < TM; i++) a[i] = As[kk][ty*TM + i];
            #pragma unroll
            for (int j = 0; j < TN; j++) bb[j] = Ws[kk][tx*TN + j];
            #pragma unroll
            for (int i = 0; i < TM; i++)
                #pragma unroll
                for (int j = 0; j < TN; j++) acc[i][j] += a[i]*bb[j];
        }
        __syncthreads();
    }
    #pragma unroll
    for (int i = 0; i < TM; i++){
        int gr = row0 + ty*TM + i;
        if (gr >= M) continue;
        #pragma unroll
        for (int j = 0; j < TN; j++)
            C[(size_t)gr*64 + tx*TN + j] = acc[i][j];
    }
}

// ---------------- CSR build ----------------
__global__ void zero_deg(){
    int i = blockIdx.x*blockDim.x + threadIdx.x;
    if (i < NN) g_deg[i] = 0;
}
__global__ void hist(const int* __restrict__ dst){
    int e = blockIdx.x*blockDim.x + threadIdx.x;
    if (e < EE) atomicAdd(&g_deg[dst[e]], 1);
}
__global__ void scan_rowptr(){
    __shared__ int wsum[32];
    int t = threadIdx.x, lane = t & 31, wid = t >> 5;
    int beg = t*20, end = beg + 20; if (end > NN) end = NN;
    int s = 0;
    for (int i = beg; i < end; i++) s += g_deg[i];
    int v = s;
    #pragma unroll
    for (int o = 1; o < 32; o <<= 1){
        int u = __shfl_up_sync(0xffffffffu, v, o);
        if (lane >= o) v += u;
    }
    if (lane == 31) wsum[wid] = v;
    __syncthreads();
    if (wid == 0){
        int w = wsum[lane];
        #pragma unroll
        for (int o = 1; o < 32; o <<= 1){
            int u = __shfl_up_sync(0xffffffffu, w, o);
            if (lane >= o) w += u;
        }
        wsum[lane] = w;
    }
    __syncthreads();
    int run = v - s + (wid ? wsum[wid-1] : 0);
    for (int i = beg; i < end; i++){
        g_rowptr[i] = run;
        g_cur[i]    = run;
        run += g_deg[i];
    }
}
__global__ void scatter(const int* __restrict__ dst){
    int e = blockIdx.x*blockDim.x + threadIdx.x;
    if (e >= EE) return;
    int slot = atomicAdd(&g_cur[dst[e]], 1);
    g_eid[slot] = e;
}

// ---------------- fused per-destination attention + aggregation (fp16 xw) -------------
// No-max softmax (logits O(1), exp-safe): one block reduction at the very end.
// Thread t owns cols {2t, 2t+1}, head h = t>>5.
__global__ void edge_fused(const int* __restrict__ src, const int* __restrict__ et,
                           const float* __restrict__ bias,
                           const float* __restrict__ skip,
                           float* __restrict__ out,
                           bf16* __restrict__ oh, bf16* __restrict__ ol)
{
    const int d = blockIdx.x;
    const int t = threadIdx.x;          // 128
    const int wid  = t >> 5, lane = t & 31;
    const int base = g_rowptr[d], deg = g_deg[d];
    const int h = t >> 5;

    __shared__ float sl[128][4];
    __shared__ int   ssrc[128];
    __shared__ int   srel[128];
    __shared__ float reds[4][4];

    float2 a[8];
    #pragma unroll
    for (int u = 0; u < 8; u++){ a[u].x = 0.f; a[u].y = 0.f; }
    float psum[4] = {0.f, 0.f, 0.f, 0.f};

    const __half2* xw2 = (const __half2*)g_xwh;

    for (int c0 = 0; c0 < deg; c0 += 128){
        int n = deg - c0; if (n > 128) n = 128;
        if (t < n){
            int e = g_eid[base + c0 + t];
            int s = src[e], r = et[e];
            ssrc[t] = s; srel[t] = r;
            float4 qv = *(const float4*)(g_s + (size_t)d*64 + r*4);
            float4 kv = *(const float4*)(g_s + (size_t)s*64 + 32 + r*4);
            float l0 = qv.x + kv.x, l1 = qv.y + kv.y;
            float l2 = qv.z + kv.z, l3 = qv.w + kv.w;
            l0 = l0 > 0.f ? l0 : 0.2f*l0;  l1 = l1 > 0.f ? l1 : 0.2f*l1;
            l2 = l2 > 0.f ? l2 : 0.2f*l2;  l3 = l3 > 0.f ? l3 : 0.2f*l3;
            float e0 = __expf(l0), e1 = __expf(l1), e2 = __expf(l2), e3 = __expf(l3);
            sl[t][0] = e0; sl[t][1] = e1; sl[t][2] = e2; sl[t][3] = e3;
            psum[0] += e0; psum[1] += e1; psum[2] += e2; psum[3] += e3;
        }
        __syncthreads();

        // message accumulation: one half2 per edge per thread, 8-deep unroll
        int i = 0;
        for (; i + 8 <= n; i += 8){
            float2 xv[8];
            #pragma unroll
            for (int u = 0; u < 8; u++){
                size_t row = ((size_t)srel[i+u]*NN + ssrc[i+u])*128;
                xv[u] = __half22float2(xw2[row + t]);
            }
            #pragma unroll
            for (int u = 0; u < 8; u++){
                float ww = sl[i+u][h];
                a[u].x += ww*xv[u].x;
                a[u].y += ww*xv[u].y;
            }
        }
        for (; i < n; i++){
            size_t row = ((size_t)srel[i]*NN + ssrc[i])*128;
            float2 xv = __half22float2(xw2[row + t]);
            float ww = sl[i][h];
            a[0].x += ww*xv.x;
            a[0].y += ww*xv.y;
        }
        __syncthreads();
    }

    // single end-of-kernel block reduction of exp sums
    #pragma unroll
    for (int hh = 0; hh < 4; hh++){
        float v = psum[hh];
        #pragma unroll
        for (int o = 16; o; o >>= 1) v += __shfl_xor_sync(0xffffffffu, v, o);
        if (lane == 0) reds[wid][hh] = v;
    }
    __syncthreads();
    float ssum = reds[0][h] + reds[1][h] + reds[2][h] + reds[3][h];

    float inv = 1.f / fmaxf(ssum, 1e-16f);
    float v0 = (((a[0].x+a[1].x) + (a[2].x+a[3].x)) + ((a[4].x+a[5].x) + (a[6].x+a[7].x)))*inv;
    float v1 = (((a[0].y+a[1].y) + (a[2].y+a[3].y)) + ((a[4].y+a[5].y) + (a[6].y+a[7].y)))*inv;
    int c0 = t*2;
    v0 += bias[c0];
    v1 += bias[c0+1];
    if (skip){
        v0 += skip[(size_t)d*HD + c0];
        v1 += skip[(size_t)d*HD + c0 + 1];
    }
    v0 = lrelu01(v0); v1 = lrelu01(v1);
    float2 vv; vv.x = v0; vv.y = v1;
    *(float2*)(out + (size_t)d*HD + c0) = vv;
    if (oh){
        bf16 hh, ll;
        split2(v0, hh, ll); oh[(size_t)d*HD + c0]     = hh; ol[(size_t)d*HD + c0]     = ll;
        split2(v1, hh, ll); oh[(size_t)d*HD + c0 + 1] = hh; ol[(size_t)d*HD + c0 + 1] = ll;
    }
}

// ---------------- host ----------------
template<typename T>
static T* sym(const void* s){ void* p = nullptr; cudaGetSymbolAddress(&p, s); return (T*)p; }

extern "C" void kernel_launch(void* const* d_in, const int* in_sizes, int n_in,
                              void* d_out, int out_size)
{
    int iKG, iCCLE, iNID, iEI, iET, iCW1, iCB1, iCW2, iCB2,
        iW1, iQ1, iK1, iB1, iW2, iQ2, iK2, iB2, iSW1, iSB1, iSW2, iSB2;
    if (in_sizes[2] == NN){
        iKG=0; iCCLE=1; iNID=2; iEI=3; iET=4;
        iCW1=5; iCB1=6; iCW2=7; iCB2=8;
        iW1=9; iQ1=10; iK1=11; iB1=12;
        iW2=13; iQ2=14; iK2=15; iB2=16;
        iSW1=17; iSB1=18; iSW2=19; iSB2=20;
    } else {
        iKG=0; iCCLE=1;
        iCW1=2; iCB1=3; iCW2=4; iCB2=5;
        iW1=6; iQ1=7; iK1=8; iB1=9;
        iW2=10; iQ2=11; iK2=12; iB2=13;
        iSW1=14; iSB1=15; iSW2=16; iSB2=17;
        iNID=18; iEI=19; iET=20;
    }
    const float* kg   = (const float*)d_in[iKG];
    const float* ccle = (const float*)d_in[iCCLE];
    const int*   nid  = (const int*)  d_in[iNID];
    const int*   ei   = (const int*)  d_in[iEI];
    const int*   et   = (const int*)  d_in[iET];
    const int*   src  = ei;
    const int*   dst  = ei + EE;
    const float* cw1 = (const float*)d_in[iCW1]; const float* cb1 = (const float*)d_in[iCB1];
    const float* cw2 = (const float*)d_in[iCW2]; const float* cb2 = (const float*)d_in[iCB2];
    const float* w1  = (const float*)d_in[iW1];  const float* q1  = (const float*)d_in[iQ1];
    const float* k1  = (const float*)d_in[iK1];  const float* b1  = (const float*)d_in[iB1];
    const float* w2  = (const float*)d_in[iW2];  const float* q2  = (const float*)d_in[iQ2];
    const float* k2  = (const float*)d_in[iK2];  const float* b2  = (const float*)d_in[iB2];
    const float* sw1 = (const float*)d_in[iSW1]; const float* sb1 = (const float*)d_in[iSB1];
    const float* sw2 = (const float*)d_in[iSW2]; const float* sb2 = (const float*)d_in[iSB2];

    float* pxin  = sym<float>(g_xin);
    __half* pxwh = sym<__half>(g_xwh);
    float* ps    = sym<float>(g_s);    float* pwqk = sym<float>(g_wqk);
    float* px1   = sym<float>(g_x1);   float* pskp = sym<float>(g_skp);
    bf16* pxinh = sym<bf16>(g_xinh);  bf16* pxinl = sym<bf16>(g_xinl);
    bf16* px1h  = sym<bf16>(g_x1h);   bf16* px1l  = sym<bf16>(g_x1l);
    bf16* phsh  = sym<bf16>(g_hsh);   bf16* phsl  = sym<bf16>(g_hsl);
    bf16* pw1h  = sym<bf16>(g_w1h);   bf16* pw1l  = sym<bf16>(g_w1l);
    bf16* pw2h  = sym<bf16>(g_w2h);   bf16* pw2l  = sym<bf16>(g_w2l);
    bf16* psw1h = sym<bf16>(g_sw1h);  bf16* psw1l = sym<bf16>(g_sw1l);
    bf16* psw2h = sym<bf16>(g_sw2h);  bf16* psw2l = sym<bf16>(g_sw2l);

    const int SMEM_HM = 3*32768;
    cudaFuncSetAttribute(hmma_gemm<0>, cudaFuncAttributeMaxDynamicSharedMemorySize, SMEM_HM);
    cudaFuncSetAttribute(hmma_gemm<1>, cudaFuncAttributeMaxDynamicSharedMemorySize, SMEM_HM);
    cudaFuncSetAttribute(hmma_gemm<2>, cudaFuncAttributeMaxDynamicSharedMemorySize, SMEM_HM);

    static cudaStream_t sS = nullptr;
    static cudaEvent_t evFork, evW1, evW2, evXin, evPre1, evSkip, evX1, evPre2;
    if (!sS){
        cudaStreamCreateWithFlags(&sS, cudaStreamNonBlocking);
        cudaEventCreateWithFlags(&evFork, cudaEventDisableTiming);
        cudaEventCreateWithFlags(&evW1,   cudaEventDisableTiming);
        cudaEventCreateWithFlags(&evW2,   cudaEventDisableTiming);
        cudaEventCreateWithFlags(&evXin,  cudaEventDisableTiming);
        cudaEventCreateWithFlags(&evPre1, cudaEventDisableTiming);
        cudaEventCreateWithFlags(&evSkip, cudaEventDisableTiming);
        cudaEventCreateWithFlags(&evX1,   cudaEventDisableTiming);
        cudaEventCreateWithFlags(&evPre2, cudaEventDisableTiming);
    }

    const int gM  = (NN + 127)/128;   // 157
    const int gM64= (NN + 63)/64;
    const int gE  = (EE + 255)/256;
    dim3 tb(32, 8);

    // ---- fork side stream ----
    cudaEventRecord(evFork, 0);
    cudaStreamWaitEvent(sS, evFork, 0);

    // main: critical path (hmma L1 at launch slot #4 for ncu)
    build_xin<<<NN, 128>>>(kg, ccle, nid, cw1, cb1, cw2, cb2);           // 1
    cudaEventRecord(evXin, 0);
    splitW<<<dim3(8,8,RR), tb, 0, sS>>>(w1, pw1h, pw1l);                 // 2
    cudaEventRecord(evW1, sS);
    make_wqk<<<64, 256, 0, sS>>>(w1, q1, k1);                            // 3
    cudaStreamWaitEvent(0, evW1, 0);
    hmma_gemm<0><<<dim3(gM,2,RR), 256, SMEM_HM>>>(pxinh, pxinl, pw1h, pw1l,
                                                  nullptr, pxwh, nullptr, nullptr, NN, nullptr,
                                                  (size_t)65536, (size_t)NN*HD);  // 4
    // side: remaining prep + CSR + skip chain
    splitW<<<dim3(8,8,RR), tb, 0, sS>>>(w2, pw2h, pw2l);
    cudaEventRecord(evW2, sS);
    zero_deg<<<(NN+255)/256, 256, 0, sS>>>();
    hist<<<gE, 256, 0, sS>>>(dst);
    scan_rowptr<<<1, 1024, 0, sS>>>();
    scatter<<<gE, 256, 0, sS>>>(dst);
    cudaStreamWaitEvent(sS, evXin, 0);
    gemm_k256_n64<<<gM64, 256, 0, sS>>>(pxin, pwqk, ps, NN);
    cudaEventRecord(evPre1, sS);
    make_wqk<<<64, 256, 0, sS>>>(w2, q2, k2);
    splitW<<<dim3(8,8,1), tb, 0, sS>>>(sw1, psw1h, psw1l);
    splitW<<<dim3(8,8,1), tb, 0, sS>>>(sw2, psw2h, psw2l);
    hmma_gemm<1><<<dim3(gM,2,1), 256, SMEM_HM, sS>>>(pxinh, pxinl, psw1h, psw1l,
                                                     nullptr, nullptr, phsh, phsl, NN, sb1, 0, 0);
    hmma_gemm<2><<<dim3(gM,2,1), 256, SMEM_HM, sS>>>(phsh, phsl, psw2h, psw2l,
                                                     pskp, nullptr, nullptr, nullptr, NN, sb2, 0, 0);
    cudaEventRecord(evSkip, sS);

    // main: edge L1
    cudaStreamWaitEvent(0, evPre1, 0);
    edge_fused<<<NN, 128>>>(src, et, b1, nullptr, px1, px1h, px1l);
    cudaEventRecord(evX1, 0);

    // side: layer-2 projection
    cudaStreamWaitEvent(sS, evX1, 0);
    gemm_k256_n64<<<gM64, 256, 0, sS>>>(px1, pwqk, ps, NN);
    cudaEventRecord(evPre2, sS);

    // main: layer-2 GEMM + final edge
    cudaStreamWaitEvent(0, evW2, 0);
    hmma_gemm<0><<<dim3(gM,2,RR), 256, SMEM_HM>>>(px1h, px1l, pw2h, pw2l,
                                                  nullptr, pxwh, nullptr, nullptr, NN, nullptr,
                                                  (size_t)65536, (size_t)NN*HD);
    cudaStreamWaitEvent(0, evSkip, 0);
    cudaStreamWaitEvent(0, evPre2, 0);
    edge_fused<<<NN, 128>>>(src, et, b2, pskp, (float*)d_out, nullptr, nullptr);
}

// round 13
// speedup vs baseline: 1.6797x; 1.4723x over previous
#include <cuda_runtime.h>
#include <cuda_fp16.h>
#include <cstdint>
#include <cstddef>

#define NN   20000
#define EE   320000
#define RR   8
#define HH   4
#define HD   256

// ---------------- device scratch ----------------
__device__ float  g_xin [(size_t)NN*HD];
__device__ __half g_xinf[(size_t)NN*HD];
__device__ __half g_xwh [(size_t)RR*NN*HD];   // fp16 xw table (82 MB)
__device__ float  g_s   [(size_t)NN*64];
__device__ float  g_wqk [256*64];
__device__ float  g_x1  [(size_t)NN*HD];
__device__ __half g_x1f [(size_t)NN*HD];
__device__ __half g_hsf [(size_t)NN*HD];
__device__ float  g_skp [(size_t)NN*HD];
__device__ __half g_wt1 [(size_t)RR*65536];
__device__ __half g_wt2 [(size_t)RR*65536];
__device__ __half g_swt1[65536];
__device__ __half g_swt2[65536];
__device__ int g_deg[NN], g_rowptr[NN], g_cur[NN], g_eid[EE];

__device__ __forceinline__ float lrelu01(float v){ return v > 0.f ? v : 0.01f*v; }

__device__ __forceinline__ uint32_t smem_u32(const void* p){
    uint32_t a;
    asm("{ .reg .u64 t; cvta.to.shared.u64 t, %1; cvt.u32.u64 %0, t; }" : "=r"(a) : "l"(p));
    return a;
}
__device__ __forceinline__ void ldsm_x4(uint32_t* r, uint32_t addr){
    asm volatile("ldmatrix.sync.aligned.m8n8.x4.shared.b16 {%0,%1,%2,%3}, [%4];"
        : "=r"(r[0]), "=r"(r[1]), "=r"(r[2]), "=r"(r[3]) : "r"(addr));
}
__device__ __forceinline__ void mma16816f(float* d, const uint32_t* a, const uint32_t* b){
    asm volatile("mma.sync.aligned.m16n8k16.row.col.f32.f16.f16.f32 "
        "{%0,%1,%2,%3}, {%4,%5,%6,%7}, {%8,%9}, {%0,%1,%2,%3};"
        : "+f"(d[0]), "+f"(d[1]), "+f"(d[2]), "+f"(d[3])
        : "r"(a[0]), "r"(a[1]), "r"(a[2]), "r"(a[3]), "r"(b[0]), "r"(b[1]));
}
__device__ __forceinline__ void cp_async16(uint32_t saddr, const void* g, uint32_t srcsz){
    asm volatile("cp.async.cg.shared.global [%0], [%1], 16, %2;"
                 :: "r"(saddr), "l"(g), "r"(srcsz) : "memory");
}
#define CP_COMMIT() asm volatile("cp.async.commit_group;" ::: "memory")
#define CP_WAIT1()  asm volatile("cp.async.wait_group 1;" ::: "memory")
#define CP_WAIT0()  asm volatile("cp.async.wait_group 0;" ::: "memory")

__device__ __forceinline__ uint32_t swz(int row, uint32_t colB){
    return (uint32_t)(row*64) + (colB ^ (uint32_t)((row & 6) << 3));
}

// ---------------- x_in build (fp32 + fp16) ----------------
__global__ void build_xin(const float* __restrict__ kg, const float* __restrict__ ccle,
                          const int* __restrict__ nid,
                          const float* __restrict__ cw1, const float* __restrict__ cb1,
                          const float* __restrict__ cw2, const float* __restrict__ cb2)
{
    int i = blockIdx.x;
    int t = threadIdx.x;               // 128
    int nd = nid[i];
    __shared__ float c4[4];
    __shared__ float hdn[32];
    if (t < 4) c4[t] = ccle[(size_t)nd*4 + t];
    float v0 = kg[(size_t)nd*128 + t];
    g_xin [(size_t)i*HD + t] = v0;
    g_xinf[(size_t)i*HD + t] = __float2half(v0);
    __syncthreads();
    if (t < 32){
        float a = cb1[t];
        #pragma unroll
        for (int j = 0; j < 4; j++) a += c4[j]*cw1[j*32 + t];
        hdn[t] = lrelu01(a);
    }
    __syncthreads();
    float o = cb2[t];
    #pragma unroll 8
    for (int j = 0; j < 32; j++) o += hdn[j]*cw2[j*128 + t];
    g_xin [(size_t)i*HD + 128 + t] = o;
    g_xinf[(size_t)i*HD + 128 + t] = __float2half(o);
}

// ---------------- W transpose + fp16 convert: w[z][k][n] -> wt[z][n][k] ----------------
__global__ void convW(const float* __restrict__ w, __half* __restrict__ o)
{
    __shared__ float tile[32][33];
    int z = blockIdx.z;
    const float* wz = w + (size_t)z*65536;
    int tx = threadIdx.x, ty = threadIdx.y;   // 32x8
    int k0 = blockIdx.x*32, n0 = blockIdx.y*32;
    #pragma unroll
    for (int i = ty; i < 32; i += 8)
        tile[i][tx] = wz[(size_t)(k0+i)*256 + n0 + tx];
    __syncthreads();
    #pragma unroll
    for (int i = ty; i < 32; i += 8)
        o[(size_t)z*65536 + (size_t)(n0+i)*256 + k0 + tx] = __float2half(tile[tx][i]);
}

// ---------------- single-pass fp16 HMMA GEMM, 3-stage cp.async, XOR swizzle -------------
// Per stage (16384 B): A@0 (8KB), W@8192 (8KB). K chunks of 32, 8 chunks.
// MODE 0: fp16 -> Ch2 (xw). MODE 1: bias+lrelu -> fp16 Ch2. MODE 2: bias -> fp32 Cf.
__device__ __forceinline__ void hm_load(uint32_t sb, int stg, int kc,
    const __half* __restrict__ A, const __half* __restrict__ WB,
    int row0, int M, int t)
{
    const int kofs = kc*32;
    const uint32_t stBase = sb + (uint32_t)stg*16384u;
    #pragma unroll
    for (int j = 0; j < 2; j++){
        int g   = j*256 + t;
        int row = g >> 2;
        uint32_t cb = (uint32_t)((g & 3) * 16);
        uint32_t so = stBase + swz(row, cb);
        uint32_t ok = (row0 + row < M) ? 16u : 0u;
        cp_async16(so,          A  + (size_t)(row0 + row)*256 + kofs + (cb >> 1), ok);
        cp_async16(so + 8192u,  WB + (size_t)row*256          + kofs + (cb >> 1), 16u);
    }
}

template<int MODE>
__global__ void __launch_bounds__(256, 2)
hmma_gemm(const __half* __restrict__ A, const __half* __restrict__ W,
          float* __restrict__ Cf, __half* __restrict__ Ch2,
          int M, const float* __restrict__ bias,
          size_t wStride, size_t cStride)
{
    extern __shared__ char sm[];
    const uint32_t sb = smem_u32(sm);
    const int t = threadIdx.x, lane = t & 31, wid = t >> 5;
    const int wm = wid & 3, wn = wid >> 2;
    const int row0 = blockIdx.x*128;
    const int col0 = blockIdx.y*128;
    const __half* WB = W + wStride*blockIdx.z + (size_t)col0*256;

    float acc[2][8][4];
    #pragma unroll
    for (int i = 0; i < 2; i++)
        #pragma unroll
        for (int j = 0; j < 8; j++)
            #pragma unroll
            for (int q = 0; q < 4; q++) acc[i][j][q] = 0.f;

    const int ar  = lane & 15, ac8 = lane >> 4;
    const int bnl = (lane & 7) + ((lane >> 4) << 3);
    const int bkh = (lane >> 3) & 1;

    hm_load(sb, 0, 0, A, WB, row0, M, t); CP_COMMIT();
    hm_load(sb, 1, 1, A, WB, row0, M, t); CP_COMMIT();

    int stg = 0, ldstg = 2;
    for (int kc = 0; kc < 8; kc++){
        if (kc < 7) CP_WAIT1(); else CP_WAIT0();
        __syncthreads();
        if (kc < 6){
            hm_load(sb, ldstg, kc+2, A, WB, row0, M, t);
            CP_COMMIT();
            if (++ldstg == 3) ldstg = 0;
        }

        const uint32_t stBase = sb + (uint32_t)stg*16384u;
        #pragma unroll
        for (int ks = 0; ks < 2; ks++){
            uint32_t af[2][4], bw[4][4];
            const uint32_t acol = (uint32_t)(ks*32 + ac8*16);
            #pragma unroll
            for (int i = 0; i < 2; i++){
                int row = wm*32 + i*16 + ar;
                ldsm_x4(af[i], stBase + swz(row, acol));
            }
            const uint32_t bcol = (uint32_t)(ks*32 + bkh*16);
            #pragma unroll
            for (int qd = 0; qd < 4; qd++){
                int row = wn*64 + qd*16 + bnl;
                ldsm_x4(bw[qd], stBase + 8192u + swz(row, bcol));
            }
            #pragma unroll
            for (int i = 0; i < 2; i++)
                #pragma unroll
                for (int j = 0; j < 8; j++)
                    mma16816f(acc[i][j], af[i], &bw[j>>1][(j&1)*2]);
        }
        if (++stg == 3) stg = 0;
    }

    const int cr = lane >> 2, cc = (lane & 3)*2;
    #pragma unroll
    for (int i = 0; i < 2; i++){
        #pragma unroll
        for (int rr = 0; rr < 2; rr++){
            int grow = row0 + wm*32 + i*16 + rr*8 + cr;
            if (grow >= M) continue;
            #pragma unroll
            for (int j = 0; j < 8; j++){
                int gcol = col0 + wn*64 + j*8 + cc;
                float v0 = acc[i][j][rr*2+0];
                float v1 = acc[i][j][rr*2+1];
                if (MODE == 0){
                    *(__half2*)(Ch2 + cStride*blockIdx.z + (size_t)grow*256 + gcol) =
                        __floats2half2_rn(v0, v1);
                } else if (MODE == 1){
                    v0 = lrelu01(v0 + bias[gcol]);
                    v1 = lrelu01(v1 + bias[gcol+1]);
                    *(__half2*)(Ch2 + (size_t)grow*256 + gcol) = __floats2half2_rn(v0, v1);
                } else {
                    float2 f; f.x = v0 + bias[gcol]; f.y = v1 + bias[gcol+1];
                    *(float2*)(Cf + (size_t)grow*256 + gcol) = f;
                }
            }
        }
    }
}

// ---------------- wqk fold + small projection GEMM (fp32, feeds g_s) ----------------
__global__ void make_wqk(const float* __restrict__ w, const float* __restrict__ q,
                         const float* __restrict__ km)
{
    int idx = blockIdx.x*blockDim.x + threadIdx.x;
    int kk  = idx >> 6;
    int j   = idx & 63;
    int isK = (j >= 32);
    int rh  = isK ? j - 32 : j;
    int r   = rh >> 2, h = rh & 3;
    const float* wm = w + ((size_t)r*256 + kk)*256;
    const float* qm = isK ? km : q;
    float a = 0.f;
    #pragma unroll 8
    for (int o = 0; o < 256; o++) a += wm[o]*qm[o*4 + h];
    g_wqk[kk*64 + j] = a;
}

__global__ void gemm_k256_n64(const float* __restrict__ A, const float* __restrict__ W,
                              float* __restrict__ C, int M)
{
    constexpr int BM = 64, BK = 16, BN = 64;
    constexpr int TN = 4, TM = 4;
    __shared__ float As[BK][BM + 4];
    __shared__ float Ws[BK][BN];
    int row0 = blockIdx.x*BM;
    int t  = threadIdx.x;
    int tx = t & 15, ty = t >> 4;
    float acc[TM][TN] = {};
    int aRow = t >> 2;
    int aK4  = (t & 3) * 4;
    for (int k0 = 0; k0 < 256; k0 += BK){
        float4 av = make_float4(0.f,0.f,0.f,0.f);
        int gr = row0 + aRow;
        if (gr < M) av = *(const float4*)(A + (size_t)gr*256 + k0 + aK4);
        As[aK4+0][aRow] = av.x; As[aK4+1][aRow] = av.y;
        As[aK4+2][aRow] = av.z; As[aK4+3][aRow] = av.w;
        {
            int kk = t / 16, j4 = (t % 16) * 4;
            *(float4*)&Ws[kk][j4] = *(const float4*)(W + (size_t)(k0+kk)*64 + j4);
        }
        __syncthreads();
        #pragma unroll
        for (int kk = 0; kk < BK; kk++){
            float a[TM], bb[TN];
            #pragma unroll
            for (int i = 0; i < TM; i++) a[i] = As[kk][ty*TM + i];
            #pragma unroll
            for (int j = 0; j < TN; j++) bb[j] = Ws[kk][tx*TN + j];
            #pragma unroll
            for (int i = 0; i < TM; i++)
                #pragma unroll
                for (int j = 0; j < TN; j++) acc[i][j] += a[i]*bb[j];
        }
        __syncthreads();
    }
    #pragma unroll
    for (int i = 0; i < TM; i++){
        int gr = row0 + ty*TM + i;
        if (gr >= M) continue;
        #pragma unroll
        for (int j = 0; j < TN; j++)
            C[(size_t)gr*64 + tx*TN + j] = acc[i][j];
    }
}

// ---------------- CSR build ----------------
__global__ void zero_deg(){
    int i = blockIdx.x*blockDim.x + threadIdx.x;
    if (i < NN) g_deg[i] = 0;
}
__global__ void hist(const int* __restrict__ dst){
    int e = blockIdx.x*blockDim.x + threadIdx.x;
    if (e < EE) atomicAdd(&g_deg[dst[e]], 1);
}
__global__ void scan_rowptr(){
    __shared__ int wsum[32];
    int t = threadIdx.x, lane = t & 31, wid = t >> 5;
    int beg = t*20, end = beg + 20; if (end > NN) end = NN;
    int s = 0;
    for (int i = beg; i < end; i++) s += g_deg[i];
    int v = s;
    #pragma unroll
    for (int o = 1; o < 32; o <<= 1){
        int u = __shfl_up_sync(0xffffffffu, v, o);
        if (lane >= o) v += u;
    }
    if (lane == 31) wsum[wid] = v;
    __syncthreads();
    if (wid == 0){
        int w = wsum[lane];
        #pragma unroll
        for (int o = 1; o < 32; o <<= 1){
            int u = __shfl_up_sync(0xffffffffu, w, o);
            if (lane >= o) w += u;
        }
        wsum[lane] = w;
    }
    __syncthreads();
    int run = v - s + (wid ? wsum[wid-1] : 0);
    for (int i = beg; i < end; i++){
        g_rowptr[i] = run;
        g_cur[i]    = run;
        run += g_deg[i];
    }
}
__global__ void scatter(const int* __restrict__ dst){
    int e = blockIdx.x*blockDim.x + threadIdx.x;
    if (e >= EE) return;
    int slot = atomicAdd(&g_cur[dst[e]], 1);
    g_eid[slot] = e;
}

// ---------------- fused per-destination attention + aggregation (fp16 xw) -------------
// No-max softmax; one block reduction at the end. Thread t owns cols {2t,2t+1}, head t>>5.
__global__ void edge_fused(const int* __restrict__ src, const int* __restrict__ et,
                           const float* __restrict__ bias,
                           const float* __restrict__ skip,
                           float* __restrict__ out,
                           __half* __restrict__ ofh)
{
    const int d = blockIdx.x;
    const int t = threadIdx.x;          // 128
    const int wid  = t >> 5, lane = t & 31;
    const int base = g_rowptr[d], deg = g_deg[d];
    const int h = t >> 5;

    __shared__ float sl[128][4];
    __shared__ int   ssrc[128];
    __shared__ int   srel[128];
    __shared__ float reds[4][4];

    float2 a[8];
    #pragma unroll
    for (int u = 0; u < 8; u++){ a[u].x = 0.f; a[u].y = 0.f; }
    float psum[4] = {0.f, 0.f, 0.f, 0.f};

    const __half2* xw2 = (const __half2*)g_xwh;

    for (int c0 = 0; c0 < deg; c0 += 128){
        int n = deg - c0; if (n > 128) n = 128;
        if (t < n){
            int e = g_eid[base + c0 + t];
            int s = src[e], r = et[e];
            ssrc[t] = s; srel[t] = r;
            float4 qv = *(const float4*)(g_s + (size_t)d*64 + r*4);
            float4 kv = *(const float4*)(g_s + (size_t)s*64 + 32 + r*4);
            float l0 = qv.x + kv.x, l1 = qv.y + kv.y;
            float l2 = qv.z + kv.z, l3 = qv.w + kv.w;
            l0 = l0 > 0.f ? l0 : 0.2f*l0;  l1 = l1 > 0.f ? l1 : 0.2f*l1;
            l2 = l2 > 0.f ? l2 : 0.2f*l2;  l3 = l3 > 0.f ? l3 : 0.2f*l3;
            float e0 = __expf(l0), e1 = __expf(l1), e2 = __expf(l2), e3 = __expf(l3);
            sl[t][0] = e0; sl[t][1] = e1; sl[t][2] = e2; sl[t][3] = e3;
            psum[0] += e0; psum[1] += e1; psum[2] += e2; psum[3] += e3;
        }
        __syncthreads();

        int i = 0;
        for (; i + 8 <= n; i += 8){
            float2 xv[8];
            #pragma unroll
            for (int u = 0; u < 8; u++){
                size_t row = ((size_t)srel[i+u]*NN + ssrc[i+u])*128;
                xv[u] = __half22float2(xw2[row + t]);
            }
            #pragma unroll
            for (int u = 0; u < 8; u++){
                float ww = sl[i+u][h];
                a[u].x += ww*xv[u].x;
                a[u].y += ww*xv[u].y;
            }
        }
        for (; i < n; i++){
            size_t row = ((size_t)srel[i]*NN + ssrc[i])*128;
            float2 xv = __half22float2(xw2[row + t]);
            float ww = sl[i][h];
            a[0].x += ww*xv.x;
            a[0].y += ww*xv.y;
        }
        __syncthreads();
    }

    #pragma unroll
    for (int hh = 0; hh < 4; hh++){
        float v = psum[hh];
        #pragma unroll
        for (int o = 16; o; o >>= 1) v += __shfl_xor_sync(0xffffffffu, v, o);
        if (lane == 0) reds[wid][hh] = v;
    }
    __syncthreads();
    float ssum = reds[0][h] + reds[1][h] + reds[2][h] + reds[3][h];

    float inv = 1.f / fmaxf(ssum, 1e-16f);
    float v0 = (((a[0].x+a[1].x) + (a[2].x+a[3].x)) + ((a[4].x+a[5].x) + (a[6].x+a[7].x)))*inv;
    float v1 = (((a[0].y+a[1].y) + (a[2].y+a[3].y)) + ((a[4].y+a[5].y) + (a[6].y+a[7].y)))*inv;
    int c0 = t*2;
    v0 += bias[c0];
    v1 += bias[c0+1];
    if (skip){
        v0 += skip[(size_t)d*HD + c0];
        v1 += skip[(size_t)d*HD + c0 + 1];
    }
    v0 = lrelu01(v0); v1 = lrelu01(v1);
    float2 vv; vv.x = v0; vv.y = v1;
    *(float2*)(out + (size_t)d*HD + c0) = vv;
    if (ofh)
        *(__half2*)(ofh + (size_t)d*HD + c0) = __floats2half2_rn(v0, v1);
}

// ---------------- host ----------------
template<typename T>
static T* sym(const void* s){ void* p = nullptr; cudaGetSymbolAddress(&p, s); return (T*)p; }

extern "C" void kernel_launch(void* const* d_in, const int* in_sizes, int n_in,
                              void* d_out, int out_size)
{
    int iKG, iCCLE, iNID, iEI, iET, iCW1, iCB1, iCW2, iCB2,
        iW1, iQ1, iK1, iB1, iW2, iQ2, iK2, iB2, iSW1, iSB1, iSW2, iSB2;
    if (in_sizes[2] == NN){
        iKG=0; iCCLE=1; iNID=2; iEI=3; iET=4;
        iCW1=5; iCB1=6; iCW2=7; iCB2=8;
        iW1=9; iQ1=10; iK1=11; iB1=12;
        iW2=13; iQ2=14; iK2=15; iB2=16;
        iSW1=17; iSB1=18; iSW2=19; iSB2=20;
    } else {
        iKG=0; iCCLE=1;
        iCW1=2; iCB1=3; iCW2=4; iCB2=5;
        iW1=6; iQ1=7; iK1=8; iB1=9;
        iW2=10; iQ2=11; iK2=12; iB2=13;
        iSW1=14; iSB1=15; iSW2=16; iSB2=17;
        iNID=18; iEI=19; iET=20;
    }
    const float* kg   = (const float*)d_in[iKG];
    const float* ccle = (const float*)d_in[iCCLE];
    const int*   nid  = (const int*)  d_in[iNID];
    const int*   ei   = (const int*)  d_in[iEI];
    const int*   et   = (const int*)  d_in[iET];
    const int*   src  = ei;
    const int*   dst  = ei + EE;
    const float* cw1 = (const float*)d_in[iCW1]; const float* cb1 = (const float*)d_in[iCB1];
    const float* cw2 = (const float*)d_in[iCW2]; const float* cb2 = (const float*)d_in[iCB2];
    const float* w1  = (const float*)d_in[iW1];  const float* q1  = (const float*)d_in[iQ1];
    const float* k1  = (const float*)d_in[iK1];  const float* b1  = (const float*)d_in[iB1];
    const float* w2  = (const float*)d_in[iW2];  const float* q2  = (const float*)d_in[iQ2];
    const float* k2  = (const float*)d_in[iK2];  const float* b2  = (const float*)d_in[iB2];
    const float* sw1 = (const float*)d_in[iSW1]; const float* sb1 = (const float*)d_in[iSB1];
    const float* sw2 = (const float*)d_in[iSW2]; const float* sb2 = (const float*)d_in[iSB2];

    float*  pxin  = sym<float>(g_xin);
    __half* pxinf = sym<__half>(g_xinf);
    __half* pxwh  = sym<__half>(g_xwh);
    float*  ps    = sym<float>(g_s);    float* pwqk = sym<float>(g_wqk);
    float*  px1   = sym<float>(g_x1);
    __half* px1f  = sym<__half>(g_x1f);
    __half* phsf  = sym<__half>(g_hsf);
    float*  pskp  = sym<float>(g_skp);
    __half* pwt1  = sym<__half>(g_wt1);  __half* pwt2  = sym<__half>(g_wt2);
    __half* pswt1 = sym<__half>(g_swt1); __half* pswt2 = sym<__half>(g_swt2);

    const int SMEM_HM = 3*16384;   // 49152 B
    cudaFuncSetAttribute(hmma_gemm<0>, cudaFuncAttributeMaxDynamicSharedMemorySize, SMEM_HM);
    cudaFuncSetAttribute(hmma_gemm<1>, cudaFuncAttributeMaxDynamicSharedMemorySize, SMEM_HM);
    cudaFuncSetAttribute(hmma_gemm<2>, cudaFuncAttributeMaxDynamicSharedMemorySize, SMEM_HM);

    static cudaStream_t sS = nullptr;
    static cudaEvent_t evFork, evW1, evW2, evXin, evPre1, evSkip, evX1, evPre2;
    if (!sS){
        cudaStreamCreateWithFlags(&sS, cudaStreamNonBlocking);
        cudaEventCreateWithFlags(&evFork, cudaEventDisableTiming);
        cudaEventCreateWithFlags(&evW1,   cudaEventDisableTiming);
        cudaEventCreateWithFlags(&evW2,   cudaEventDisableTiming);
        cudaEventCreateWithFlags(&evXin,  cudaEventDisableTiming);
        cudaEventCreateWithFlags(&evPre1, cudaEventDisableTiming);
        cudaEventCreateWithFlags(&evSkip, cudaEventDisableTiming);
        cudaEventCreateWithFlags(&evX1,   cudaEventDisableTiming);
        cudaEventCreateWithFlags(&evPre2, cudaEventDisableTiming);
    }

    const int gM  = (NN + 127)/128;   // 157
    const int gM64= (NN + 63)/64;
    const int gE  = (EE + 255)/256;
    dim3 tb(32, 8);

    // ---- fork side stream ----
    cudaEventRecord(evFork, 0);
    cudaStreamWaitEvent(sS, evFork, 0);

    // main: critical path (hmma L1 at launch slot #4 for ncu)
    build_xin<<<NN, 128>>>(kg, ccle, nid, cw1, cb1, cw2, cb2);           // 1
    cudaEventRecord(evXin, 0);
    convW<<<dim3(8,8,RR), tb, 0, sS>>>(w1, pwt1);                        // 2
    cudaEventRecord(evW1, sS);
    make_wqk<<<64, 256, 0, sS>>>(w1, q1, k1);                            // 3
    cudaStreamWaitEvent(0, evW1, 0);
    hmma_gemm<0><<<dim3(gM,2,RR), 256, SMEM_HM>>>(pxinf, pwt1,
                                                  nullptr, pxwh, NN, nullptr,
                                                  (size_t)65536, (size_t)NN*HD);  // 4
    // side: remaining prep + CSR + skip chain
    convW<<<dim3(8,8,RR), tb, 0, sS>>>(w2, pwt2);
    cudaEventRecord(evW2, sS);
    zero_deg<<<(NN+255)/256, 256, 0, sS>>>();
    hist<<<gE, 256, 0, sS>>>(dst);
    scan_rowptr<<<1, 1024, 0, sS>>>();
    scatter<<<gE, 256, 0, sS>>>(dst);
    cudaStreamWaitEvent(sS, evXin, 0);
    gemm_k256_n64<<<gM64, 256, 0, sS>>>(pxin, pwqk, ps, NN);
    cudaEventRecord(evPre1, sS);
    make_wqk<<<64, 256, 0, sS>>>(w2, q2, k2);
    convW<<<dim3(8,8,1), tb, 0, sS>>>(sw1, pswt1);
    convW<<<dim3(8,8,1), tb, 0, sS>>>(sw2, pswt2);
    hmma_gemm<1><<<dim3(gM,2,1), 256, SMEM_HM, sS>>>(pxinf, pswt1,
                                                     nullptr, phsf, NN, sb1, 0, 0);
    hmma_gemm<2><<<dim3(gM,2,1), 256, SMEM_HM, sS>>>(phsf, pswt2,
                                                     pskp, nullptr, NN, sb2, 0, 0);
    cudaEventRecord(evSkip, sS);

    // main: edge L1
    cudaStreamWaitEvent(0, evPre1, 0);
    edge_fused<<<NN, 128>>>(src, et, b1, nullptr, px1, px1f);
    cudaEventRecord(evX1, 0);

    // side: layer-2 projection
    cudaStreamWaitEvent(sS, evX1, 0);
    gemm_k256_n64<<<gM64, 256, 0, sS>>>(px1, pwqk, ps, NN);
    cudaEventRecord(evPre2, sS);

    // main: layer-2 GEMM + final edge
    cudaStreamWaitEvent(0, evW2, 0);
    hmma_gemm<0><<<dim3(gM,2,RR), 256, SMEM_HM>>>(px1f, pwt2,
                                                  nullptr, pxwh, NN, nullptr,
                                                  (size_t)65536, (size_t)NN*HD);
    cudaStreamWaitEvent(0, evSkip, 0);
    cudaStreamWaitEvent(0, evPre2, 0);
    edge_fused<<<NN, 128>>>(src, et, b2, pskp, (float*)d_out, nullptr);
}